// round 13
// baseline (speedup 1.0000x reference)
#include <cuda_runtime.h>

#define Bn 1024
#define Tn 128
#define Hd 64
#define NZv 5
#define ACTD 20
#define Rr 16
#define SCAN_BLOCKS 64
#define EPS_T_BLOCKS 256                     // 256 blocks x 256 threads = 65536 outputs per timestep
#define EPS_TOTAL ((Tn + 1) * EPS_T_BLOCKS)  // 33024 eps blocks

typedef unsigned long long ull;

// ---------------- device scratch (static allocation only) ----------------
__device__ float g_eps[(size_t)(Tn + 1) * Bn * Hd];     // (T+1,B,H)
__device__ float g_kld[SCAN_BLOCKS];                    // per-block partial sums
__device__ int   g_done[Tn + 1];                        // zero-init at load; reset by reducer
__device__ int   g_scan_done;                           // ditto
__device__ unsigned g_one = 1;   // runtime-opaque 1: forces adds onto IMAD (fma pipe)

// ---------------- f32x2 packed helpers ----------------
__device__ __forceinline__ ull pk2(float lo, float hi) {
    ull r; asm("mov.b64 %0, {%1, %2};" : "=l"(r) : "f"(lo), "f"(hi)); return r;
}
__device__ __forceinline__ void unpk2(ull v, float& lo, float& hi) {
    asm("mov.b64 {%0, %1}, %2;" : "=f"(lo), "=f"(hi) : "l"(v));
}
__device__ __forceinline__ ull pki2(unsigned lo, unsigned hi) {
    ull r; asm("mov.b64 %0, {%1, %2};" : "=l"(r) : "r"(lo), "r"(hi)); return r;
}
__device__ __forceinline__ ull fma2(ull a, ull b, ull c) {
    ull d; asm("fma.rn.f32x2 %0, %1, %2, %3;" : "=l"(d) : "l"(a), "l"(b), "l"(c)); return d;
}
__device__ __forceinline__ ull add2(ull a, ull b) {
    ull d; asm("add.rn.f32x2 %0, %1, %2;" : "=l"(d) : "l"(a), "l"(b)); return d;
}
__device__ __forceinline__ ull dup2(float x) { return pk2(x, x); }

// ---------------- math helpers ----------------
__device__ __forceinline__ float softplusf(float x) {
    return fmaxf(x, 0.0f) + log1pf(expf(-fabsf(x)));
}
__device__ __forceinline__ float sigmoidf(float x) {
    return 1.0f / (1.0f + expf(-x));
}
__device__ __forceinline__ unsigned imadd(unsigned a, unsigned b, unsigned one) {
    unsigned d;
    asm("mad.lo.u32 %0, %1, %2, %3;" : "=r"(d) : "r"(a), "r"(one), "r"(b));
    return d;
}
__device__ __forceinline__ float poly_main(float wk) {
    float p = 2.81022636e-08f;
    p = fmaf(p, wk, 3.43273939e-07f);
    p = fmaf(p, wk, -3.5233877e-06f);
    p = fmaf(p, wk, -4.39150654e-06f);
    p = fmaf(p, wk, 0.00021858087f);
    p = fmaf(p, wk, -0.00125372503f);
    p = fmaf(p, wk, -0.00417768164f);
    p = fmaf(p, wk, 0.246640727f);
    p = fmaf(p, wk, 1.50140941f);
    return p;
}
__device__ __forceinline__ float poly_tail(float w) {
    float ws = sqrtf(w) - 3.0f;
    float p = -0.000200214257f;
    p = fmaf(p, ws, 0.000100950558f);
    p = fmaf(p, ws, 0.00134934322f);
    p = fmaf(p, ws, -0.00367342844f);
    p = fmaf(p, ws, 0.00573950773f);
    p = fmaf(p, ws, -0.0076224613f);
    p = fmaf(p, ws, 0.00943887047f);
    p = fmaf(p, ws, 1.00167406f);
    p = fmaf(p, ws, 2.83297682f);
    return p;
}

// general threefry (prologue key fold only)
__device__ __forceinline__ uint2 threefry2x32(unsigned k0, unsigned k1,
                                              unsigned x0, unsigned x1) {
    unsigned ks2 = k0 ^ k1 ^ 0x1BD11BDAu;
#define TF_RND(r) { x0 += x1; x1 = __funnelshift_l(x1, x1, r); x1 ^= x0; }
    x0 += k0; x1 += k1;
    TF_RND(13) TF_RND(15) TF_RND(26) TF_RND(6)
    x0 += k1;  x1 += ks2 + 1u;
    TF_RND(17) TF_RND(29) TF_RND(16) TF_RND(24)
    x0 += ks2; x1 += k0 + 2u;
    TF_RND(13) TF_RND(15) TF_RND(26) TF_RND(6)
    x0 += k0;  x1 += k1 + 3u;
    TF_RND(17) TF_RND(29) TF_RND(16) TF_RND(24)
    x0 += k1;  x1 += ks2 + 4u;
    TF_RND(13) TF_RND(15) TF_RND(26) TF_RND(6)
    x0 += ks2; x1 += k0 + 5u;
#undef TF_RND
    uint2 r; r.x = x0; r.y = x1; return r;
}

// hot path: counter word0 == 0, adds on fma pipe; returns y0 ^ y1.
// Rotates ALTERNATE between two encodings to balance pipe pressure:
//   TF_S: SHF(alu) + LOP3(alu)
//   TF_W: IMAD.WIDE(fma) + fused (lo|hi)^x0 LOP3(alu)   [rotl via x * 2^r]
__device__ __forceinline__ unsigned tf_xor(
    unsigned k0, unsigned k1, unsigned ks2,
    unsigned c1, unsigned c2, unsigned c3, unsigned c4, unsigned c5,
    unsigned e, unsigned k1d, unsigned one)
{
    unsigned x0 = k0;
    unsigned x1 = imadd(e, k1d, one);
#define TF_S(r) { x0 = imadd(x1, x0, one); x1 = __funnelshift_l(x1, x1, r); x1 ^= x0; }
#define TF_W(r) { x0 = imadd(x1, x0, one); \
    ull w_; asm("mul.wide.u32 %0, %1, %2;" : "=l"(w_) : "r"(x1), "r"(1u << (r))); \
    x1 = ((unsigned)w_ | (unsigned)(w_ >> 32)) ^ x0; }
    TF_W(13) TF_S(15) TF_W(26) TF_S(6)
    x0 = imadd(k1, x0, one);  x1 = imadd(c1, x1, one);
    TF_W(17) TF_S(29) TF_W(16) TF_S(24)
    x0 = imadd(ks2, x0, one); x1 = imadd(c2, x1, one);
    TF_W(13) TF_S(15) TF_W(26) TF_S(6)
    x0 = imadd(k0, x0, one);  x1 = imadd(c3, x1, one);
    TF_W(17) TF_S(29) TF_W(16) TF_S(24)
    x0 = imadd(k1, x0, one);  x1 = imadd(c4, x1, one);
    TF_W(13) TF_S(15) TF_W(26) TF_S(6)
    x0 = imadd(ks2, x0, one); x1 = imadd(c5, x1, one);
#undef TF_S
#undef TF_W
    return x0 ^ x1;
}

// mantissa word via funnel shift: (bits>>9) | 0x3F800000 in ONE SHF
__device__ __forceinline__ unsigned mant(unsigned bits) {
    return __funnelshift_r(bits, 0x7Fu, 9);
}

// ============================================================================
// EPS role (R9/R12 structure; cipher pipe-balanced)
// ============================================================================
__device__ __noinline__ void eps_role(int eb) {
    const int tid = threadIdx.x;
    const int t = eb >> 8;
    const unsigned bz = (unsigned)((eb & 255) * 256 + tid);
    const int gid = t * (Bn * Hd) + (int)bz;

    const unsigned one = g_one;
    uint2 kk = threefry2x32(0u, 42u, 0u, (unsigned)t);
    const unsigned k0 = kk.x, k1 = kk.y;
    const unsigned ks2 = k0 ^ k1 ^ 0x1BD11BDAu;
    const unsigned c1 = ks2 + 1u, c2 = k0 + 2u, c3 = k1 + 3u,
                   c4 = ks2 + 4u, c5 = k0 + 5u;
    const unsigned k1d0 = k1, k1d1 = k1 + 65536u,
                   k1d2 = k1 + 131072u, k1d3 = k1 + 196608u;

    const ull NEGONE2  = dup2(-1.0f);
    const ull TWO2     = dup2(2.0f);
    const ull NEGP2    = dup2(-0.99999994f);
    const ull NEGLN2_2 = dup2(-0.69314718f);
    const ull M2P5_2   = dup2(-2.5f);
    const ull P0 = dup2(2.81022636e-08f);
    const ull P1 = dup2(3.43273939e-07f);
    const ull P2 = dup2(-3.5233877e-06f);
    const ull P3 = dup2(-4.39150654e-06f);
    const ull P4 = dup2(0.00021858087f);
    const ull P5 = dup2(-0.00125372503f);
    const ull P6 = dup2(-0.00417768164f);
    const ull P7 = dup2(0.246640727f);
    const ull P8 = dup2(1.50140941f);

    ull sumA = 0ull, sumB = 0ull;
    unsigned e = bz;
    const unsigned step = 262144u;

    #pragma unroll 2
    for (int s = 0; s < 250; s++) {
        unsigned b0 = tf_xor(k0, k1, ks2, c1, c2, c3, c4, c5, e, k1d0, one);
        unsigned b1 = tf_xor(k0, k1, ks2, c1, c2, c3, c4, c5, e, k1d1, one);
        unsigned b2 = tf_xor(k0, k1, ks2, c1, c2, c3, c4, c5, e, k1d2, one);
        unsigned b3 = tf_xor(k0, k1, ks2, c1, c2, c3, c4, c5, e, k1d3, one);

        ull gA = pki2(mant(b0), mant(b1));
        ull gB = pki2(mant(b2), mant(b3));
        ull fA = add2(gA, NEGONE2);
        ull fB = add2(gB, NEGONE2);
        ull uA = fma2(fA, TWO2, NEGP2);
        ull uB = fma2(fB, TWO2, NEGP2);
        ull tA = fma2(uA, uA, NEGONE2);
        ull tB = fma2(uB, uB, NEGONE2);
        float t0, t1, t2, t3;
        unpk2(tA, t0, t1); unpk2(tB, t2, t3);
        float tm = fmaxf(fmaxf(t0, t1), fmaxf(t2, t3));

        if (__builtin_expect(tm >= -6.737947e-3f, 0)) {
            float u0, u1, u2, u3;
            unpk2(uA, u0, u1); unpk2(uB, u2, u3);
            float uu[4] = {u0, u1, u2, u3};
            float tt[4] = {t0, t1, t2, t3};
            float cc[4];
            #pragma unroll
            for (int i = 0; i < 4; i++) {
                float l = __log2f(-tt[i]);
                float w = l * -0.69314718f;
                float pv;
                if (w < 5.0f) pv = poly_main(fmaf(l, -0.69314718f, -2.5f));
                else          pv = poly_tail(w);
                cc[i] = pv * uu[i];
            }
            sumA = add2(sumA, pk2(cc[0], cc[1]));
            sumB = add2(sumB, pk2(cc[2], cc[3]));
        } else {
            float l0 = __log2f(-t0), l1 = __log2f(-t1);
            float l2 = __log2f(-t2), l3 = __log2f(-t3);
            ull wkA = fma2(pk2(l0, l1), NEGLN2_2, M2P5_2);
            ull wkB = fma2(pk2(l2, l3), NEGLN2_2, M2P5_2);
            ull pA = fma2(P0, wkA, P1);
            ull pB = fma2(P0, wkB, P1);
            pA = fma2(pA, wkA, P2);  pB = fma2(pB, wkB, P2);
            pA = fma2(pA, wkA, P3);  pB = fma2(pB, wkB, P3);
            pA = fma2(pA, wkA, P4);  pB = fma2(pB, wkB, P4);
            pA = fma2(pA, wkA, P5);  pB = fma2(pB, wkB, P5);
            pA = fma2(pA, wkA, P6);  pB = fma2(pB, wkB, P6);
            pA = fma2(pA, wkA, P7);  pB = fma2(pB, wkB, P7);
            pA = fma2(pA, wkA, P8);  pB = fma2(pB, wkB, P8);
            sumA = fma2(pA, uA, sumA);
            sumB = fma2(pB, uB, sumB);
        }
        e = imadd(step, e, one);
    }
    float s0, s1, s2, s3;
    unpk2(sumA, s0, s1); unpk2(sumB, s2, s3);
    g_eps[gid] = ((s0 + s1) + (s2 + s3)) * (1.41421356f * 0.001f);

    __threadfence();
    __syncthreads();
    if (tid == 0) atomicAdd(&g_done[t], 1);
}

// ============================================================================
// SCAN role: 16 rows/block, 64 blocks (unchanged from R12)
// ============================================================================
__device__ void scan_role(
    int sb,
    const int* __restrict__ acts, const float* __restrict__ durs,
    const float* __restrict__ W_act, const float* __restrict__ b_act,
    const float* __restrict__ W_dur, const float* __restrict__ b_dur,
    const float* __restrict__ W_x,  const float* __restrict__ b_x,
    const float* __restrict__ W_z,  const float* __restrict__ b_z,
    const float* __restrict__ Wp1,  const float* __restrict__ bp1,
    const float* __restrict__ Wp2,  const float* __restrict__ bp2,
    const float* __restrict__ Wq1,  const float* __restrict__ bq1,
    const float* __restrict__ Wq2,  const float* __restrict__ bq2,
    const float* __restrict__ W_dec,const float* __restrict__ b_dec,
    const float* __restrict__ W_a,  const float* __restrict__ b_a,
    const float* __restrict__ W_durd,const float* __restrict__ b_durd,
    const float* __restrict__ W_ih, const float* __restrict__ W_hh,
    const float* __restrict__ b_ih, const float* __restrict__ b_hh,
    const float* __restrict__ gpost,const float* __restrict__ gprior,
    float* __restrict__ out)
{
    __shared__ float sh[Rr][Hd];
    __shared__ float sx[Rr][Hd];
    __shared__ float u_buf[Rr][2 * Hd];
    __shared__ float u_big[Rr * NZv * Hd];
    __shared__ float s_mp[Rr][Hd];
    __shared__ float s_mq[Rr][Hd];
    __shared__ float s_logit[Rr][ACTD];

#define S_INP(r,c)  u_buf[r][c]
#define S_Z(r,j)    u_buf[r][j]
#define S_PZ(r,j)   u_buf[r][Hd + (j)]
#define S_H1(r,n,o) u_big[(((r) * NZv) + (n)) * Hd + (o)]
#define S_GI(lr,k)  u_big[(lr) * 192 + (k)]
#define S_GH(lr,k)  u_big[1536 + (lr) * 192 + (k)]

    const int tid = threadIdx.x;
    const int row0 = sb * Rr;
    float kl_acc = 0.0f;

    for (int idx = tid; idx < Rr * Hd; idx += 256) sh[idx >> 6][idx & 63] = 0.f;
    __syncthreads();

    for (int t = 0; t < Tn; t++) {
        // ---- S0: embed input ----
        for (int idx = tid; idx < Rr * 2 * Hd; idx += 256) {
            int r = idx >> 7, c = idx & 127;
            float v;
            if (c < Hd) {
                int a = acts[(row0 + r) * Tn + t];
                v = W_act[a * Hd + c] + b_act[c];
            } else {
                float du = durs[(row0 + r) * Tn + t];
                v = fmaf(du, W_dur[c - Hd], b_dur[c - Hd]);
            }
            S_INP(r, c) = fmaxf(v, 0.f);
        }
        __syncthreads();

        // ---- phi_x ----
        for (int u = tid; u < Rr * 32; u += 256) {
            int r = u >> 5, j0 = (u & 31) * 2;
            float a0 = b_x[j0], a1 = b_x[j0 + 1];
            const float2* w2 = (const float2*)(W_x + j0);
            #pragma unroll 8
            for (int i = 0; i < 2 * Hd; i++) {
                float xv = S_INP(r, i);
                float2 wv = w2[i * 32];
                a0 = fmaf(xv, wv.x, a0);
                a1 = fmaf(xv, wv.y, a1);
            }
            sx[r][j0]     = fmaxf(a0, 0.f);
            sx[r][j0 + 1] = fmaxf(a1, 0.f);
        }
        __syncthreads();

        // ---- S1: post h1 ----
        for (int u = tid; u < 8 * NZv * 16; u += 256) {
            int r2 = u / 80, rem = u % 80;
            int n = rem >> 4, o0 = (rem & 15) * 4;
            int r0 = r2 * 2;
            const float4* w4 = (const float4*)(Wp1 + (size_t)n * 8192 + o0);
            float4 bb = *(const float4*)(bp1 + n * Hd + o0);
            float4 a0 = bb, a1 = bb;
            #pragma unroll 8
            for (int i = 0; i < Hd; i++) {
                float xa = sx[r0][i], xb = sx[r0 + 1][i];
                float4 wv = w4[i * 16];
                a0.x=fmaf(xa,wv.x,a0.x); a0.y=fmaf(xa,wv.y,a0.y); a0.z=fmaf(xa,wv.z,a0.z); a0.w=fmaf(xa,wv.w,a0.w);
                a1.x=fmaf(xb,wv.x,a1.x); a1.y=fmaf(xb,wv.y,a1.y); a1.z=fmaf(xb,wv.z,a1.z); a1.w=fmaf(xb,wv.w,a1.w);
            }
            #pragma unroll 8
            for (int i = 0; i < Hd; i++) {
                float xa = sh[r0][i], xb = sh[r0 + 1][i];
                float4 wv = w4[(Hd + i) * 16];
                a0.x=fmaf(xa,wv.x,a0.x); a0.y=fmaf(xa,wv.y,a0.y); a0.z=fmaf(xa,wv.z,a0.z); a0.w=fmaf(xa,wv.w,a0.w);
                a1.x=fmaf(xb,wv.x,a1.x); a1.y=fmaf(xb,wv.y,a1.y); a1.z=fmaf(xb,wv.z,a1.z); a1.w=fmaf(xb,wv.w,a1.w);
            }
            float* d0 = &S_H1(r0, n, o0);
            float* d1 = &S_H1(r0 + 1, n, o0);
            d0[0]=fmaxf(a0.x,0.f); d0[1]=fmaxf(a0.y,0.f); d0[2]=fmaxf(a0.z,0.f); d0[3]=fmaxf(a0.w,0.f);
            d1[0]=fmaxf(a1.x,0.f); d1[1]=fmaxf(a1.y,0.f); d1[2]=fmaxf(a1.z,0.f); d1[3]=fmaxf(a1.w,0.f);
        }
        __syncthreads();

        // ---- S2: m_post ----
        for (int u = tid; u < Rr * 32; u += 256) {
            int r = u >> 5, z0 = (u & 31) * 2;
            float m0 = 0.f, m1 = 0.f;
            for (int n = 0; n < NZv; n++) {
                float t0a = bp2[n * Hd + z0], t1a = bp2[n * Hd + z0 + 1];
                const float2* w2 = (const float2*)(Wp2 + (size_t)n * 4096 + z0);
                #pragma unroll 8
                for (int o = 0; o < Hd; o++) {
                    float hv = S_H1(r, n, o);
                    float2 wv = w2[o * 32];
                    t0a = fmaf(hv, wv.x, t0a);
                    t1a = fmaf(hv, wv.y, t1a);
                }
                float g = gpost[n];
                m0 = fmaf(g, t0a, m0);
                m1 = fmaf(g, t1a, m1);
            }
            s_mp[r][z0] = m0; s_mp[r][z0 + 1] = m1;
        }
        __syncthreads();

        // ---- S3: prior h1 ----
        for (int u = tid; u < 8 * NZv * 16; u += 256) {
            int r2 = u / 80, rem = u % 80;
            int n = rem >> 4, o0 = (rem & 15) * 4;
            int r0 = r2 * 2;
            const float4* w4 = (const float4*)(Wq1 + (size_t)n * 4096 + o0);
            float4 bb = *(const float4*)(bq1 + n * Hd + o0);
            float4 a0 = bb, a1 = bb;
            #pragma unroll 8
            for (int i = 0; i < Hd; i++) {
                float xa = sh[r0][i], xb = sh[r0 + 1][i];
                float4 wv = w4[i * 16];
                a0.x=fmaf(xa,wv.x,a0.x); a0.y=fmaf(xa,wv.y,a0.y); a0.z=fmaf(xa,wv.z,a0.z); a0.w=fmaf(xa,wv.w,a0.w);
                a1.x=fmaf(xb,wv.x,a1.x); a1.y=fmaf(xb,wv.y,a1.y); a1.z=fmaf(xb,wv.z,a1.z); a1.w=fmaf(xb,wv.w,a1.w);
            }
            float* d0 = &S_H1(r0, n, o0);
            float* d1 = &S_H1(r0 + 1, n, o0);
            d0[0]=fmaxf(a0.x,0.f); d0[1]=fmaxf(a0.y,0.f); d0[2]=fmaxf(a0.z,0.f); d0[3]=fmaxf(a0.w,0.f);
            d1[0]=fmaxf(a1.x,0.f); d1[1]=fmaxf(a1.y,0.f); d1[2]=fmaxf(a1.z,0.f); d1[3]=fmaxf(a1.w,0.f);
        }
        __syncthreads();

        // ---- S4: m_prior ----
        for (int u = tid; u < Rr * 32; u += 256) {
            int r = u >> 5, z0 = (u & 31) * 2;
            float m0 = 0.f, m1 = 0.f;
            for (int n = 0; n < NZv; n++) {
                float t0a = bq2[n * Hd + z0], t1a = bq2[n * Hd + z0 + 1];
                const float2* w2 = (const float2*)(Wq2 + (size_t)n * 4096 + z0);
                #pragma unroll 8
                for (int o = 0; o < Hd; o++) {
                    float hv = S_H1(r, n, o);
                    float2 wv = w2[o * 32];
                    t0a = fmaf(hv, wv.x, t0a);
                    t1a = fmaf(hv, wv.y, t1a);
                }
                float g = gprior[n];
                m0 = fmaf(g, t0a, m0);
                m1 = fmaf(g, t1a, m1);
            }
            s_mq[r][z0] = m0; s_mq[r][z0 + 1] = m1;
        }
        __syncthreads();

        // ---- wait for eps slice t ----
        if (tid == 0) {
            while (atomicAdd(&g_done[t], 0) < EPS_T_BLOCKS) __nanosleep(200);
            __threadfence();
        }
        __syncthreads();

        // ---- S5: KL + z ----
        for (int u = tid; u < Rr * 32; u += 256) {
            int r = u >> 5, z0 = (u & 31) * 2;
            const float* ep = g_eps + ((size_t)t * Bn + row0 + r) * Hd + z0;
            #pragma unroll
            for (int q = 0; q < 2; q++) {
                float mp = s_mp[r][z0 + q], mq = s_mq[r][z0 + q];
                float pm = fmaxf(mp, 0.0f), qm = fmaxf(mq, 0.0f);
                float ps = softplusf(mp),   qs = softplusf(mq);
                float d = pm - qm;
                kl_acc += logf(qs / ps) + (ps * ps + d * d) / (2.0f * qs * qs) - 0.5f;
                S_Z(r, z0 + q) = fmaf(ps, ep[q], pm);
            }
        }
        __syncthreads();

        // ---- S6: phi_z ----
        for (int u = tid; u < Rr * 32; u += 256) {
            int r = u >> 5, j0 = (u & 31) * 2;
            float a0 = b_z[j0], a1 = b_z[j0 + 1];
            const float2* w2 = (const float2*)(W_z + j0);
            #pragma unroll 8
            for (int i = 0; i < Hd; i++) {
                float xv = S_Z(r, i);
                float2 wv = w2[i * 32];
                a0 = fmaf(xv, wv.x, a0);
                a1 = fmaf(xv, wv.y, a1);
            }
            S_PZ(r, j0)     = fmaxf(a0, 0.f);
            S_PZ(r, j0 + 1) = fmaxf(a1, 0.f);
        }
        __syncthreads();

        // ---- S7/S8: GRU, two 8-row passes ----
        #pragma unroll
        for (int pass = 0; pass < 2; pass++) {
            int rb = pass * 8;
            for (int u = tid; u < 384; u += 256) {
                if (u < 192) {
                    int r2 = u / 48, k0i = (u % 48) * 4;
                    int r0 = rb + r2 * 2;
                    const float4* w4 = (const float4*)(W_ih + k0i);
                    float4 bb = *(const float4*)(b_ih + k0i);
                    float4 a0 = bb, a1 = bb;
                    #pragma unroll 8
                    for (int i = 0; i < Hd; i++) {
                        float xa = sx[r0][i], xb = sx[r0 + 1][i];
                        float4 wv = w4[i * 48];
                        a0.x=fmaf(xa,wv.x,a0.x); a0.y=fmaf(xa,wv.y,a0.y); a0.z=fmaf(xa,wv.z,a0.z); a0.w=fmaf(xa,wv.w,a0.w);
                        a1.x=fmaf(xb,wv.x,a1.x); a1.y=fmaf(xb,wv.y,a1.y); a1.z=fmaf(xb,wv.z,a1.z); a1.w=fmaf(xb,wv.w,a1.w);
                    }
                    #pragma unroll 8
                    for (int i = 0; i < Hd; i++) {
                        float xa = S_PZ(r0, i), xb = S_PZ(r0 + 1, i);
                        float4 wv = w4[(Hd + i) * 48];
                        a0.x=fmaf(xa,wv.x,a0.x); a0.y=fmaf(xa,wv.y,a0.y); a0.z=fmaf(xa,wv.z,a0.z); a0.w=fmaf(xa,wv.w,a0.w);
                        a1.x=fmaf(xb,wv.x,a1.x); a1.y=fmaf(xb,wv.y,a1.y); a1.z=fmaf(xb,wv.z,a1.z); a1.w=fmaf(xb,wv.w,a1.w);
                    }
                    *(float4*)&S_GI(r2 * 2, k0i)     = a0;
                    *(float4*)&S_GI(r2 * 2 + 1, k0i) = a1;
                } else {
                    int gu = u - 192;
                    int r2 = gu / 48, k0i = (gu % 48) * 4;
                    int r0 = rb + r2 * 2;
                    const float4* w4 = (const float4*)(W_hh + k0i);
                    float4 bb = *(const float4*)(b_hh + k0i);
                    float4 a0 = bb, a1 = bb;
                    #pragma unroll 8
                    for (int i = 0; i < Hd; i++) {
                        float xa = sh[r0][i], xb = sh[r0 + 1][i];
                        float4 wv = w4[i * 48];
                        a0.x=fmaf(xa,wv.x,a0.x); a0.y=fmaf(xa,wv.y,a0.y); a0.z=fmaf(xa,wv.z,a0.z); a0.w=fmaf(xa,wv.w,a0.w);
                        a1.x=fmaf(xb,wv.x,a1.x); a1.y=fmaf(xb,wv.y,a1.y); a1.z=fmaf(xb,wv.z,a1.z); a1.w=fmaf(xb,wv.w,a1.w);
                    }
                    *(float4*)&S_GH(r2 * 2, k0i)     = a0;
                    *(float4*)&S_GH(r2 * 2 + 1, k0i) = a1;
                }
            }
            __syncthreads();
            for (int idx = tid; idx < 512; idx += 256) {
                int lr = idx >> 6, j = idx & 63;
                int r = rb + lr;
                float ir = S_GI(lr, j), iz = S_GI(lr, Hd + j), in_ = S_GI(lr, 2 * Hd + j);
                float hr = S_GH(lr, j), hz = S_GH(lr, Hd + j), hn  = S_GH(lr, 2 * Hd + j);
                float rg = sigmoidf(ir + hr);
                float zz = sigmoidf(iz + hz);
                float nn = tanhf(fmaf(rg, hn, in_));
                sh[r][j] = (1.0f - zz) * nn + zz * sh[r][j];
            }
            __syncthreads();
        }
    }

    // ---------- epilogue ----------
    for (int u = tid; u < 8 * NZv * 16; u += 256) {
        int r2 = u / 80, rem = u % 80;
        int n = rem >> 4, o0 = (rem & 15) * 4;
        int r0 = r2 * 2;
        const float4* w4 = (const float4*)(Wq1 + (size_t)n * 4096 + o0);
        float4 bb = *(const float4*)(bq1 + n * Hd + o0);
        float4 a0 = bb, a1 = bb;
        #pragma unroll 8
        for (int i = 0; i < Hd; i++) {
            float xa = sh[r0][i], xb = sh[r0 + 1][i];
            float4 wv = w4[i * 16];
            a0.x=fmaf(xa,wv.x,a0.x); a0.y=fmaf(xa,wv.y,a0.y); a0.z=fmaf(xa,wv.z,a0.z); a0.w=fmaf(xa,wv.w,a0.w);
            a1.x=fmaf(xb,wv.x,a1.x); a1.y=fmaf(xb,wv.y,a1.y); a1.z=fmaf(xb,wv.z,a1.z); a1.w=fmaf(xb,wv.w,a1.w);
        }
        float* d0 = &S_H1(r0, n, o0);
        float* d1 = &S_H1(r0 + 1, n, o0);
        d0[0]=fmaxf(a0.x,0.f); d0[1]=fmaxf(a0.y,0.f); d0[2]=fmaxf(a0.z,0.f); d0[3]=fmaxf(a0.w,0.f);
        d1[0]=fmaxf(a1.x,0.f); d1[1]=fmaxf(a1.y,0.f); d1[2]=fmaxf(a1.z,0.f); d1[3]=fmaxf(a1.w,0.f);
    }
    if (tid == 0) {
        while (atomicAdd(&g_done[Tn], 0) < EPS_T_BLOCKS) __nanosleep(200);
        __threadfence();
    }
    __syncthreads();
    for (int u = tid; u < Rr * 32; u += 256) {
        int r = u >> 5, z0 = (u & 31) * 2;
        float m0 = 0.f, m1 = 0.f;
        for (int n = 0; n < NZv; n++) {
            float t0a = bq2[n * Hd + z0], t1a = bq2[n * Hd + z0 + 1];
            const float2* w2 = (const float2*)(Wq2 + (size_t)n * 4096 + z0);
            #pragma unroll 8
            for (int o = 0; o < Hd; o++) {
                float hv = S_H1(r, n, o);
                float2 wv = w2[o * 32];
                t0a = fmaf(hv, wv.x, t0a);
                t1a = fmaf(hv, wv.y, t1a);
            }
            float g = gprior[n];
            m0 = fmaf(g, t0a, m0);
            m1 = fmaf(g, t1a, m1);
        }
        const float* ep = g_eps + ((size_t)Tn * Bn + row0 + r) * Hd + z0;
        S_Z(r, z0)     = fmaf(softplusf(m0), ep[0], fmaxf(m0, 0.f));
        S_Z(r, z0 + 1) = fmaf(softplusf(m1), ep[1], fmaxf(m1, 0.f));
    }
    __syncthreads();
    for (int u = tid; u < Rr * 32; u += 256) {
        int r = u >> 5, j0 = (u & 31) * 2;
        float a0 = b_z[j0], a1 = b_z[j0 + 1];
        const float2* w2 = (const float2*)(W_z + j0);
        #pragma unroll 8
        for (int i = 0; i < Hd; i++) {
            float xv = S_Z(r, i);
            float2 wv = w2[i * 32];
            a0 = fmaf(xv, wv.x, a0);
            a1 = fmaf(xv, wv.y, a1);
        }
        S_PZ(r, j0)     = fmaxf(a0, 0.f);
        S_PZ(r, j0 + 1) = fmaxf(a1, 0.f);
    }
    __syncthreads();
    for (int u = tid; u < Rr * 32; u += 256) {
        int r = u >> 5, j0 = (u & 31) * 2;
        float a0 = b_dec[j0], a1 = b_dec[j0 + 1];
        const float2* w2 = (const float2*)(W_dec + j0);
        #pragma unroll 8
        for (int i = 0; i < Hd; i++) {
            float xv = S_PZ(r, i);
            float2 wv = w2[i * 32];
            a0 = fmaf(xv, wv.x, a0);
            a1 = fmaf(xv, wv.y, a1);
        }
        #pragma unroll 8
        for (int i = 0; i < Hd; i++) {
            float xv = sh[r][i];
            float2 wv = w2[(Hd + i) * 32];
            a0 = fmaf(xv, wv.x, a0);
            a1 = fmaf(xv, wv.y, a1);
        }
        sx[r][j0]     = fmaxf(a0, 0.f);
        sx[r][j0 + 1] = fmaxf(a1, 0.f);
    }
    __syncthreads();
    for (int u = tid; u < Rr * ACTD; u += 256) {
        int r = u / ACTD, a = u % ACTD;
        float acc = b_a[a];
        #pragma unroll 8
        for (int j = 0; j < Hd; j++) acc = fmaf(sx[r][j], W_a[j * ACTD + a], acc);
        s_logit[r][a] = acc;
        out[(size_t)(row0 + r) * ACTD + a] = acc;
    }
    __syncthreads();
    for (int u = tid; u < Rr * 32; u += 256) {
        int r = u >> 5, j0 = (u & 31) * 2;
        float a0 = b_act[j0], a1 = b_act[j0 + 1];
        const float2* w2 = (const float2*)(W_act + j0);
        #pragma unroll
        for (int a = 0; a < ACTD; a++) {
            float xv = s_logit[r][a];
            float2 wv = w2[a * 32];
            a0 = fmaf(xv, wv.x, a0);
            a1 = fmaf(xv, wv.y, a1);
        }
        s_mp[r][j0]     = fmaxf(a0, 0.f);
        s_mp[r][j0 + 1] = fmaxf(a1, 0.f);
    }
    __syncthreads();
    if (tid < Rr) {
        int r = tid;
        float acc = b_durd[0];
        #pragma unroll 8
        for (int j = 0; j < Hd; j++) acc = fmaf(s_mp[r][j], W_durd[j], acc);
        #pragma unroll 8
        for (int j = 0; j < Hd; j++) acc = fmaf(sx[r][j], W_durd[Hd + j], acc);
        out[(size_t)Bn * ACTD + row0 + r] = acc;
        out[(size_t)Bn * ACTD + Bn + row0 + r] = softplusf(acc);
    }
    __syncthreads();

    // ---------- block-wide KL reduction ----------
    {
        float* rs = (float*)u_buf;
        rs[tid] = kl_acc;
        __syncthreads();
        for (int st = 128; st > 0; st >>= 1) {
            if (tid < st) rs[tid] += rs[tid + st];
            __syncthreads();
        }
        if (tid == 0) g_kld[sb] = rs[0];
    }

    // ---------- finalization ----------
    __threadfence();
    __syncthreads();
    if (tid == 0) atomicAdd(&g_scan_done, 1);

    if (sb == 0) {
        float* rs = (float*)u_buf;
        if (tid == 0) {
            while (atomicAdd(&g_scan_done, 0) < SCAN_BLOCKS) __nanosleep(200);
            __threadfence();
        }
        __syncthreads();
        rs[tid] = (tid < SCAN_BLOCKS) ? g_kld[tid] : 0.f;
        __syncthreads();
        for (int st = 128; st > 0; st >>= 1) {
            if (tid < st) rs[tid] += rs[tid + st];
            __syncthreads();
        }
        if (tid == 0) out[(size_t)Bn * ACTD + 2 * Bn] = rs[0] * (1.0f / Bn);
        if (tid <= Tn) g_done[tid] = 0;
        if (tid == 0) g_scan_done = 0;
    }
#undef S_INP
#undef S_Z
#undef S_PZ
#undef S_H1
#undef S_GI
#undef S_GH
}

// ============================================================================
// fused kernel: blocks [0,64) = scan (wave-1 resident), rest = eps
// ============================================================================
__global__ void __launch_bounds__(256) fused_kernel(
    const int* __restrict__ acts, const float* __restrict__ durs,
    const float* __restrict__ W_act, const float* __restrict__ b_act,
    const float* __restrict__ W_dur, const float* __restrict__ b_dur,
    const float* __restrict__ W_x,  const float* __restrict__ b_x,
    const float* __restrict__ W_z,  const float* __restrict__ b_z,
    const float* __restrict__ Wp1,  const float* __restrict__ bp1,
    const float* __restrict__ Wp2,  const float* __restrict__ bp2,
    const float* __restrict__ Wq1,  const float* __restrict__ bq1,
    const float* __restrict__ Wq2,  const float* __restrict__ bq2,
    const float* __restrict__ W_dec,const float* __restrict__ b_dec,
    const float* __restrict__ W_a,  const float* __restrict__ b_a,
    const float* __restrict__ W_durd,const float* __restrict__ b_durd,
    const float* __restrict__ W_ih, const float* __restrict__ W_hh,
    const float* __restrict__ b_ih, const float* __restrict__ b_hh,
    const float* __restrict__ gpost,const float* __restrict__ gprior,
    float* __restrict__ out)
{
    if (blockIdx.x >= SCAN_BLOCKS) {
        eps_role(blockIdx.x - SCAN_BLOCKS);
    } else {
        scan_role(blockIdx.x,
                  acts, durs, W_act, b_act, W_dur, b_dur, W_x, b_x, W_z, b_z,
                  Wp1, bp1, Wp2, bp2, Wq1, bq1, Wq2, bq2, W_dec, b_dec,
                  W_a, b_a, W_durd, b_durd, W_ih, W_hh, b_ih, b_hh,
                  gpost, gprior, out);
    }
}

// ---------------- launch ----------------
extern "C" void kernel_launch(void* const* d_in, const int* in_sizes, int n_in,
                              void* d_out, int out_size) {
    const int*   acts   = (const int*)  d_in[0];
    const float* durs   = (const float*)d_in[1];
    const float* W_act  = (const float*)d_in[2];
    const float* b_act  = (const float*)d_in[3];
    const float* W_dur  = (const float*)d_in[4];
    const float* b_dur  = (const float*)d_in[5];
    const float* W_x    = (const float*)d_in[6];
    const float* b_x    = (const float*)d_in[7];
    const float* W_z    = (const float*)d_in[8];
    const float* b_z    = (const float*)d_in[9];
    const float* Wp1    = (const float*)d_in[10];
    const float* bp1    = (const float*)d_in[11];
    const float* Wp2    = (const float*)d_in[12];
    const float* bp2    = (const float*)d_in[13];
    const float* Wq1    = (const float*)d_in[14];
    const float* bq1    = (const float*)d_in[15];
    const float* Wq2    = (const float*)d_in[16];
    const float* bq2    = (const float*)d_in[17];
    const float* W_dec  = (const float*)d_in[18];
    const float* b_dec  = (const float*)d_in[19];
    const float* W_a    = (const float*)d_in[20];
    const float* b_a    = (const float*)d_in[21];
    const float* W_durd = (const float*)d_in[22];
    const float* b_durd = (const float*)d_in[23];
    const float* W_ih   = (const float*)d_in[24];
    const float* W_hh   = (const float*)d_in[25];
    const float* b_ih   = (const float*)d_in[26];
    const float* b_hh   = (const float*)d_in[27];
    const float* gpost  = (const float*)d_in[28];
    const float* gprior = (const float*)d_in[29];
    float* out = (float*)d_out;

    fused_kernel<<<SCAN_BLOCKS + EPS_TOTAL, 256>>>(
        acts, durs, W_act, b_act, W_dur, b_dur, W_x, b_x, W_z, b_z,
        Wp1, bp1, Wp2, bp2, Wq1, bq1, Wq2, bq2, W_dec, b_dec,
        W_a, b_a, W_durd, b_durd, W_ih, W_hh, b_ih, b_hh,
        gpost, gprior, out);
}

// round 14
// speedup vs baseline: 1.0855x; 1.0855x over previous
#include <cuda_runtime.h>

#define Bn 1024
#define Tn 128
#define Hd 64
#define NZv 5
#define ACTD 20
#define Rr 16
#define SCAN_BLOCKS 64
#define EPS_T_BLOCKS 256                     // 256 blocks x 256 threads = 65536 outputs per timestep
#define EPS_TOTAL ((Tn + 1) * EPS_T_BLOCKS)  // 33024 eps blocks

typedef unsigned long long ull;

// ---------------- device scratch (static allocation only) ----------------
__device__ float g_eps[(size_t)(Tn + 1) * Bn * Hd];     // (T+1,B,H)
__device__ float g_kld[SCAN_BLOCKS];                    // per-block partial sums
__device__ int   g_done[Tn + 1];                        // zero-init at load; reset by reducer
__device__ int   g_scan_done;                           // ditto
__device__ unsigned g_one = 1;   // runtime-opaque 1: forces adds onto IMAD (fma pipe)

// ---------------- f32x2 packed helpers ----------------
__device__ __forceinline__ ull pk2(float lo, float hi) {
    ull r; asm("mov.b64 %0, {%1, %2};" : "=l"(r) : "f"(lo), "f"(hi)); return r;
}
__device__ __forceinline__ void unpk2(ull v, float& lo, float& hi) {
    asm("mov.b64 {%0, %1}, %2;" : "=f"(lo), "=f"(hi) : "l"(v));
}
__device__ __forceinline__ ull pki2(unsigned lo, unsigned hi) {
    ull r; asm("mov.b64 %0, {%1, %2};" : "=l"(r) : "r"(lo), "r"(hi)); return r;
}
__device__ __forceinline__ ull fma2(ull a, ull b, ull c) {
    ull d; asm("fma.rn.f32x2 %0, %1, %2, %3;" : "=l"(d) : "l"(a), "l"(b), "l"(c)); return d;
}
__device__ __forceinline__ ull add2(ull a, ull b) {
    ull d; asm("add.rn.f32x2 %0, %1, %2;" : "=l"(d) : "l"(a), "l"(b)); return d;
}
__device__ __forceinline__ ull dup2(float x) { return pk2(x, x); }

// ---------------- math helpers ----------------
__device__ __forceinline__ float softplusf(float x) {
    return fmaxf(x, 0.0f) + log1pf(expf(-fabsf(x)));
}
__device__ __forceinline__ float sigmoidf(float x) {
    return 1.0f / (1.0f + expf(-x));
}
__device__ __forceinline__ unsigned imadd(unsigned a, unsigned b, unsigned one) {
    unsigned d;
    asm("mad.lo.u32 %0, %1, %2, %3;" : "=r"(d) : "r"(a), "r"(one), "r"(b));
    return d;
}
__device__ __forceinline__ float poly_main(float wk) {
    float p = 2.81022636e-08f;
    p = fmaf(p, wk, 3.43273939e-07f);
    p = fmaf(p, wk, -3.5233877e-06f);
    p = fmaf(p, wk, -4.39150654e-06f);
    p = fmaf(p, wk, 0.00021858087f);
    p = fmaf(p, wk, -0.00125372503f);
    p = fmaf(p, wk, -0.00417768164f);
    p = fmaf(p, wk, 0.246640727f);
    p = fmaf(p, wk, 1.50140941f);
    return p;
}
__device__ __forceinline__ float poly_tail(float w) {
    float ws = sqrtf(w) - 3.0f;
    float p = -0.000200214257f;
    p = fmaf(p, ws, 0.000100950558f);
    p = fmaf(p, ws, 0.00134934322f);
    p = fmaf(p, ws, -0.00367342844f);
    p = fmaf(p, ws, 0.00573950773f);
    p = fmaf(p, ws, -0.0076224613f);
    p = fmaf(p, ws, 0.00943887047f);
    p = fmaf(p, ws, 1.00167406f);
    p = fmaf(p, ws, 2.83297682f);
    return p;
}

// general threefry (prologue key fold only)
__device__ __forceinline__ uint2 threefry2x32(unsigned k0, unsigned k1,
                                              unsigned x0, unsigned x1) {
    unsigned ks2 = k0 ^ k1 ^ 0x1BD11BDAu;
#define TF_RND(r) { x0 += x1; x1 = __funnelshift_l(x1, x1, r); x1 ^= x0; }
    x0 += k0; x1 += k1;
    TF_RND(13) TF_RND(15) TF_RND(26) TF_RND(6)
    x0 += k1;  x1 += ks2 + 1u;
    TF_RND(17) TF_RND(29) TF_RND(16) TF_RND(24)
    x0 += ks2; x1 += k0 + 2u;
    TF_RND(13) TF_RND(15) TF_RND(26) TF_RND(6)
    x0 += k0;  x1 += k1 + 3u;
    TF_RND(17) TF_RND(29) TF_RND(16) TF_RND(24)
    x0 += k1;  x1 += ks2 + 4u;
    TF_RND(13) TF_RND(15) TF_RND(26) TF_RND(6)
    x0 += ks2; x1 += k0 + 5u;
#undef TF_RND
    uint2 r; r.x = x0; r.y = x1; return r;
}

// hot path: counter word0 == 0; R12 structure + IADD3 folds.
// Key-injection x0-adds fuse with the following round's x0 += x1 into one
// 3-input add (IADD3, alu pipe): issue -1 each, 4 folds per block.
// Remaining standalone adds stay IMAD (fma pipe). Returns y0 ^ y1.
__device__ __forceinline__ unsigned tf_xor(
    unsigned k0, unsigned k1, unsigned ks2,
    unsigned c1, unsigned c2, unsigned c3, unsigned c4, unsigned c5,
    unsigned e, unsigned k1d, unsigned one)
{
    unsigned x1 = imadd(e, k1d, one);
    // round 1 fused init: x0 = e + k1d + k0 (IADD3; also independent of x1's reg)
    unsigned x0 = e + k1d + k0;
    x1 = __funnelshift_l(x1, x1, 13); x1 ^= x0;
#define TF_S(r) { x0 = imadd(x1, x0, one); x1 = __funnelshift_l(x1, x1, r); x1 ^= x0; }
// injection fold: x1 += c; x0 = x0 + k + x1 (IADD3); rotate-xor of round r
#define TF_INJ(r, kx, cx) { \
    x1 = imadd(cx, x1, one); \
    x0 = (x0 + (kx)) + x1; \
    x1 = __funnelshift_l(x1, x1, r); x1 ^= x0; }
    TF_S(15) TF_S(26) TF_S(6)
    TF_INJ(17, k1, c1)
    TF_S(29) TF_S(16) TF_S(24)
    TF_INJ(13, ks2, c2)
    TF_S(15) TF_S(26) TF_S(6)
    TF_INJ(17, k0, c3)
    TF_S(29) TF_S(16) TF_S(24)
    TF_INJ(13, k1, c4)
    TF_S(15) TF_S(26) TF_S(6)
    x0 = imadd(ks2, x0, one); x1 = imadd(c5, x1, one);
#undef TF_S
#undef TF_INJ
    return x0 ^ x1;
}

// mantissa word via funnel shift: (bits>>9) | 0x3F800000 in ONE SHF
__device__ __forceinline__ unsigned mant(unsigned bits) {
    return __funnelshift_r(bits, 0x7Fu, 9);
}

// ============================================================================
// EPS role (R12 structure; cipher with IADD3 folds)
// ============================================================================
__device__ __noinline__ void eps_role(int eb) {
    const int tid = threadIdx.x;
    const int t = eb >> 8;
    const unsigned bz = (unsigned)((eb & 255) * 256 + tid);
    const int gid = t * (Bn * Hd) + (int)bz;

    const unsigned one = g_one;
    uint2 kk = threefry2x32(0u, 42u, 0u, (unsigned)t);
    const unsigned k0 = kk.x, k1 = kk.y;
    const unsigned ks2 = k0 ^ k1 ^ 0x1BD11BDAu;
    const unsigned c1 = ks2 + 1u, c2 = k0 + 2u, c3 = k1 + 3u,
                   c4 = ks2 + 4u, c5 = k0 + 5u;
    const unsigned k1d0 = k1, k1d1 = k1 + 65536u,
                   k1d2 = k1 + 131072u, k1d3 = k1 + 196608u;

    const ull NEGONE2  = dup2(-1.0f);
    const ull TWO2     = dup2(2.0f);
    const ull NEGP2    = dup2(-0.99999994f);
    const ull NEGLN2_2 = dup2(-0.69314718f);
    const ull M2P5_2   = dup2(-2.5f);
    const ull P0 = dup2(2.81022636e-08f);
    const ull P1 = dup2(3.43273939e-07f);
    const ull P2 = dup2(-3.5233877e-06f);
    const ull P3 = dup2(-4.39150654e-06f);
    const ull P4 = dup2(0.00021858087f);
    const ull P5 = dup2(-0.00125372503f);
    const ull P6 = dup2(-0.00417768164f);
    const ull P7 = dup2(0.246640727f);
    const ull P8 = dup2(1.50140941f);

    ull sumA = 0ull, sumB = 0ull;
    unsigned e = bz;
    const unsigned step = 262144u;

    #pragma unroll 2
    for (int s = 0; s < 250; s++) {
        unsigned b0 = tf_xor(k0, k1, ks2, c1, c2, c3, c4, c5, e, k1d0, one);
        unsigned b1 = tf_xor(k0, k1, ks2, c1, c2, c3, c4, c5, e, k1d1, one);
        unsigned b2 = tf_xor(k0, k1, ks2, c1, c2, c3, c4, c5, e, k1d2, one);
        unsigned b3 = tf_xor(k0, k1, ks2, c1, c2, c3, c4, c5, e, k1d3, one);

        ull gA = pki2(mant(b0), mant(b1));
        ull gB = pki2(mant(b2), mant(b3));
        ull fA = add2(gA, NEGONE2);
        ull fB = add2(gB, NEGONE2);
        ull uA = fma2(fA, TWO2, NEGP2);
        ull uB = fma2(fB, TWO2, NEGP2);
        ull tA = fma2(uA, uA, NEGONE2);
        ull tB = fma2(uB, uB, NEGONE2);
        float t0, t1, t2, t3;
        unpk2(tA, t0, t1); unpk2(tB, t2, t3);
        float tm = fmaxf(fmaxf(t0, t1), fmaxf(t2, t3));

        if (__builtin_expect(tm >= -6.737947e-3f, 0)) {
            float u0, u1, u2, u3;
            unpk2(uA, u0, u1); unpk2(uB, u2, u3);
            float uu[4] = {u0, u1, u2, u3};
            float tt[4] = {t0, t1, t2, t3};
            float cc[4];
            #pragma unroll
            for (int i = 0; i < 4; i++) {
                float l = __log2f(-tt[i]);
                float w = l * -0.69314718f;
                float pv;
                if (w < 5.0f) pv = poly_main(fmaf(l, -0.69314718f, -2.5f));
                else          pv = poly_tail(w);
                cc[i] = pv * uu[i];
            }
            sumA = add2(sumA, pk2(cc[0], cc[1]));
            sumB = add2(sumB, pk2(cc[2], cc[3]));
        } else {
            float l0 = __log2f(-t0), l1 = __log2f(-t1);
            float l2 = __log2f(-t2), l3 = __log2f(-t3);
            ull wkA = fma2(pk2(l0, l1), NEGLN2_2, M2P5_2);
            ull wkB = fma2(pk2(l2, l3), NEGLN2_2, M2P5_2);
            ull pA = fma2(P0, wkA, P1);
            ull pB = fma2(P0, wkB, P1);
            pA = fma2(pA, wkA, P2);  pB = fma2(pB, wkB, P2);
            pA = fma2(pA, wkA, P3);  pB = fma2(pB, wkB, P3);
            pA = fma2(pA, wkA, P4);  pB = fma2(pB, wkB, P4);
            pA = fma2(pA, wkA, P5);  pB = fma2(pB, wkB, P5);
            pA = fma2(pA, wkA, P6);  pB = fma2(pB, wkB, P6);
            pA = fma2(pA, wkA, P7);  pB = fma2(pB, wkB, P7);
            pA = fma2(pA, wkA, P8);  pB = fma2(pB, wkB, P8);
            sumA = fma2(pA, uA, sumA);
            sumB = fma2(pB, uB, sumB);
        }
        e = imadd(step, e, one);
    }
    float s0, s1, s2, s3;
    unpk2(sumA, s0, s1); unpk2(sumB, s2, s3);
    g_eps[gid] = ((s0 + s1) + (s2 + s3)) * (1.41421356f * 0.001f);

    __threadfence();
    __syncthreads();
    if (tid == 0) atomicAdd(&g_done[t], 1);
}

// ============================================================================
// SCAN role: 16 rows/block, 64 blocks (unchanged from R12)
// ============================================================================
__device__ void scan_role(
    int sb,
    const int* __restrict__ acts, const float* __restrict__ durs,
    const float* __restrict__ W_act, const float* __restrict__ b_act,
    const float* __restrict__ W_dur, const float* __restrict__ b_dur,
    const float* __restrict__ W_x,  const float* __restrict__ b_x,
    const float* __restrict__ W_z,  const float* __restrict__ b_z,
    const float* __restrict__ Wp1,  const float* __restrict__ bp1,
    const float* __restrict__ Wp2,  const float* __restrict__ bp2,
    const float* __restrict__ Wq1,  const float* __restrict__ bq1,
    const float* __restrict__ Wq2,  const float* __restrict__ bq2,
    const float* __restrict__ W_dec,const float* __restrict__ b_dec,
    const float* __restrict__ W_a,  const float* __restrict__ b_a,
    const float* __restrict__ W_durd,const float* __restrict__ b_durd,
    const float* __restrict__ W_ih, const float* __restrict__ W_hh,
    const float* __restrict__ b_ih, const float* __restrict__ b_hh,
    const float* __restrict__ gpost,const float* __restrict__ gprior,
    float* __restrict__ out)
{
    __shared__ float sh[Rr][Hd];
    __shared__ float sx[Rr][Hd];
    __shared__ float u_buf[Rr][2 * Hd];
    __shared__ float u_big[Rr * NZv * Hd];
    __shared__ float s_mp[Rr][Hd];
    __shared__ float s_mq[Rr][Hd];
    __shared__ float s_logit[Rr][ACTD];

#define S_INP(r,c)  u_buf[r][c]
#define S_Z(r,j)    u_buf[r][j]
#define S_PZ(r,j)   u_buf[r][Hd + (j)]
#define S_H1(r,n,o) u_big[(((r) * NZv) + (n)) * Hd + (o)]
#define S_GI(lr,k)  u_big[(lr) * 192 + (k)]
#define S_GH(lr,k)  u_big[1536 + (lr) * 192 + (k)]

    const int tid = threadIdx.x;
    const int row0 = sb * Rr;
    float kl_acc = 0.0f;

    for (int idx = tid; idx < Rr * Hd; idx += 256) sh[idx >> 6][idx & 63] = 0.f;
    __syncthreads();

    for (int t = 0; t < Tn; t++) {
        // ---- S0: embed input ----
        for (int idx = tid; idx < Rr * 2 * Hd; idx += 256) {
            int r = idx >> 7, c = idx & 127;
            float v;
            if (c < Hd) {
                int a = acts[(row0 + r) * Tn + t];
                v = W_act[a * Hd + c] + b_act[c];
            } else {
                float du = durs[(row0 + r) * Tn + t];
                v = fmaf(du, W_dur[c - Hd], b_dur[c - Hd]);
            }
            S_INP(r, c) = fmaxf(v, 0.f);
        }
        __syncthreads();

        // ---- phi_x ----
        for (int u = tid; u < Rr * 32; u += 256) {
            int r = u >> 5, j0 = (u & 31) * 2;
            float a0 = b_x[j0], a1 = b_x[j0 + 1];
            const float2* w2 = (const float2*)(W_x + j0);
            #pragma unroll 8
            for (int i = 0; i < 2 * Hd; i++) {
                float xv = S_INP(r, i);
                float2 wv = w2[i * 32];
                a0 = fmaf(xv, wv.x, a0);
                a1 = fmaf(xv, wv.y, a1);
            }
            sx[r][j0]     = fmaxf(a0, 0.f);
            sx[r][j0 + 1] = fmaxf(a1, 0.f);
        }
        __syncthreads();

        // ---- S1: post h1 ----
        for (int u = tid; u < 8 * NZv * 16; u += 256) {
            int r2 = u / 80, rem = u % 80;
            int n = rem >> 4, o0 = (rem & 15) * 4;
            int r0 = r2 * 2;
            const float4* w4 = (const float4*)(Wp1 + (size_t)n * 8192 + o0);
            float4 bb = *(const float4*)(bp1 + n * Hd + o0);
            float4 a0 = bb, a1 = bb;
            #pragma unroll 8
            for (int i = 0; i < Hd; i++) {
                float xa = sx[r0][i], xb = sx[r0 + 1][i];
                float4 wv = w4[i * 16];
                a0.x=fmaf(xa,wv.x,a0.x); a0.y=fmaf(xa,wv.y,a0.y); a0.z=fmaf(xa,wv.z,a0.z); a0.w=fmaf(xa,wv.w,a0.w);
                a1.x=fmaf(xb,wv.x,a1.x); a1.y=fmaf(xb,wv.y,a1.y); a1.z=fmaf(xb,wv.z,a1.z); a1.w=fmaf(xb,wv.w,a1.w);
            }
            #pragma unroll 8
            for (int i = 0; i < Hd; i++) {
                float xa = sh[r0][i], xb = sh[r0 + 1][i];
                float4 wv = w4[(Hd + i) * 16];
                a0.x=fmaf(xa,wv.x,a0.x); a0.y=fmaf(xa,wv.y,a0.y); a0.z=fmaf(xa,wv.z,a0.z); a0.w=fmaf(xa,wv.w,a0.w);
                a1.x=fmaf(xb,wv.x,a1.x); a1.y=fmaf(xb,wv.y,a1.y); a1.z=fmaf(xb,wv.z,a1.z); a1.w=fmaf(xb,wv.w,a1.w);
            }
            float* d0 = &S_H1(r0, n, o0);
            float* d1 = &S_H1(r0 + 1, n, o0);
            d0[0]=fmaxf(a0.x,0.f); d0[1]=fmaxf(a0.y,0.f); d0[2]=fmaxf(a0.z,0.f); d0[3]=fmaxf(a0.w,0.f);
            d1[0]=fmaxf(a1.x,0.f); d1[1]=fmaxf(a1.y,0.f); d1[2]=fmaxf(a1.z,0.f); d1[3]=fmaxf(a1.w,0.f);
        }
        __syncthreads();

        // ---- S2: m_post ----
        for (int u = tid; u < Rr * 32; u += 256) {
            int r = u >> 5, z0 = (u & 31) * 2;
            float m0 = 0.f, m1 = 0.f;
            for (int n = 0; n < NZv; n++) {
                float t0a = bp2[n * Hd + z0], t1a = bp2[n * Hd + z0 + 1];
                const float2* w2 = (const float2*)(Wp2 + (size_t)n * 4096 + z0);
                #pragma unroll 8
                for (int o = 0; o < Hd; o++) {
                    float hv = S_H1(r, n, o);
                    float2 wv = w2[o * 32];
                    t0a = fmaf(hv, wv.x, t0a);
                    t1a = fmaf(hv, wv.y, t1a);
                }
                float g = gpost[n];
                m0 = fmaf(g, t0a, m0);
                m1 = fmaf(g, t1a, m1);
            }
            s_mp[r][z0] = m0; s_mp[r][z0 + 1] = m1;
        }
        __syncthreads();

        // ---- S3: prior h1 ----
        for (int u = tid; u < 8 * NZv * 16; u += 256) {
            int r2 = u / 80, rem = u % 80;
            int n = rem >> 4, o0 = (rem & 15) * 4;
            int r0 = r2 * 2;
            const float4* w4 = (const float4*)(Wq1 + (size_t)n * 4096 + o0);
            float4 bb = *(const float4*)(bq1 + n * Hd + o0);
            float4 a0 = bb, a1 = bb;
            #pragma unroll 8
            for (int i = 0; i < Hd; i++) {
                float xa = sh[r0][i], xb = sh[r0 + 1][i];
                float4 wv = w4[i * 16];
                a0.x=fmaf(xa,wv.x,a0.x); a0.y=fmaf(xa,wv.y,a0.y); a0.z=fmaf(xa,wv.z,a0.z); a0.w=fmaf(xa,wv.w,a0.w);
                a1.x=fmaf(xb,wv.x,a1.x); a1.y=fmaf(xb,wv.y,a1.y); a1.z=fmaf(xb,wv.z,a1.z); a1.w=fmaf(xb,wv.w,a1.w);
            }
            float* d0 = &S_H1(r0, n, o0);
            float* d1 = &S_H1(r0 + 1, n, o0);
            d0[0]=fmaxf(a0.x,0.f); d0[1]=fmaxf(a0.y,0.f); d0[2]=fmaxf(a0.z,0.f); d0[3]=fmaxf(a0.w,0.f);
            d1[0]=fmaxf(a1.x,0.f); d1[1]=fmaxf(a1.y,0.f); d1[2]=fmaxf(a1.z,0.f); d1[3]=fmaxf(a1.w,0.f);
        }
        __syncthreads();

        // ---- S4: m_prior ----
        for (int u = tid; u < Rr * 32; u += 256) {
            int r = u >> 5, z0 = (u & 31) * 2;
            float m0 = 0.f, m1 = 0.f;
            for (int n = 0; n < NZv; n++) {
                float t0a = bq2[n * Hd + z0], t1a = bq2[n * Hd + z0 + 1];
                const float2* w2 = (const float2*)(Wq2 + (size_t)n * 4096 + z0);
                #pragma unroll 8
                for (int o = 0; o < Hd; o++) {
                    float hv = S_H1(r, n, o);
                    float2 wv = w2[o * 32];
                    t0a = fmaf(hv, wv.x, t0a);
                    t1a = fmaf(hv, wv.y, t1a);
                }
                float g = gprior[n];
                m0 = fmaf(g, t0a, m0);
                m1 = fmaf(g, t1a, m1);
            }
            s_mq[r][z0] = m0; s_mq[r][z0 + 1] = m1;
        }
        __syncthreads();

        // ---- wait for eps slice t ----
        if (tid == 0) {
            while (atomicAdd(&g_done[t], 0) < EPS_T_BLOCKS) __nanosleep(200);
            __threadfence();
        }
        __syncthreads();

        // ---- S5: KL + z ----
        for (int u = tid; u < Rr * 32; u += 256) {
            int r = u >> 5, z0 = (u & 31) * 2;
            const float* ep = g_eps + ((size_t)t * Bn + row0 + r) * Hd + z0;
            #pragma unroll
            for (int q = 0; q < 2; q++) {
                float mp = s_mp[r][z0 + q], mq = s_mq[r][z0 + q];
                float pm = fmaxf(mp, 0.0f), qm = fmaxf(mq, 0.0f);
                float ps = softplusf(mp),   qs = softplusf(mq);
                float d = pm - qm;
                kl_acc += logf(qs / ps) + (ps * ps + d * d) / (2.0f * qs * qs) - 0.5f;
                S_Z(r, z0 + q) = fmaf(ps, ep[q], pm);
            }
        }
        __syncthreads();

        // ---- S6: phi_z ----
        for (int u = tid; u < Rr * 32; u += 256) {
            int r = u >> 5, j0 = (u & 31) * 2;
            float a0 = b_z[j0], a1 = b_z[j0 + 1];
            const float2* w2 = (const float2*)(W_z + j0);
            #pragma unroll 8
            for (int i = 0; i < Hd; i++) {
                float xv = S_Z(r, i);
                float2 wv = w2[i * 32];
                a0 = fmaf(xv, wv.x, a0);
                a1 = fmaf(xv, wv.y, a1);
            }
            S_PZ(r, j0)     = fmaxf(a0, 0.f);
            S_PZ(r, j0 + 1) = fmaxf(a1, 0.f);
        }
        __syncthreads();

        // ---- S7/S8: GRU, two 8-row passes ----
        #pragma unroll
        for (int pass = 0; pass < 2; pass++) {
            int rb = pass * 8;
            for (int u = tid; u < 384; u += 256) {
                if (u < 192) {
                    int r2 = u / 48, k0i = (u % 48) * 4;
                    int r0 = rb + r2 * 2;
                    const float4* w4 = (const float4*)(W_ih + k0i);
                    float4 bb = *(const float4*)(b_ih + k0i);
                    float4 a0 = bb, a1 = bb;
                    #pragma unroll 8
                    for (int i = 0; i < Hd; i++) {
                        float xa = sx[r0][i], xb = sx[r0 + 1][i];
                        float4 wv = w4[i * 48];
                        a0.x=fmaf(xa,wv.x,a0.x); a0.y=fmaf(xa,wv.y,a0.y); a0.z=fmaf(xa,wv.z,a0.z); a0.w=fmaf(xa,wv.w,a0.w);
                        a1.x=fmaf(xb,wv.x,a1.x); a1.y=fmaf(xb,wv.y,a1.y); a1.z=fmaf(xb,wv.z,a1.z); a1.w=fmaf(xb,wv.w,a1.w);
                    }
                    #pragma unroll 8
                    for (int i = 0; i < Hd; i++) {
                        float xa = S_PZ(r0, i), xb = S_PZ(r0 + 1, i);
                        float4 wv = w4[(Hd + i) * 48];
                        a0.x=fmaf(xa,wv.x,a0.x); a0.y=fmaf(xa,wv.y,a0.y); a0.z=fmaf(xa,wv.z,a0.z); a0.w=fmaf(xa,wv.w,a0.w);
                        a1.x=fmaf(xb,wv.x,a1.x); a1.y=fmaf(xb,wv.y,a1.y); a1.z=fmaf(xb,wv.z,a1.z); a1.w=fmaf(xb,wv.w,a1.w);
                    }
                    *(float4*)&S_GI(r2 * 2, k0i)     = a0;
                    *(float4*)&S_GI(r2 * 2 + 1, k0i) = a1;
                } else {
                    int gu = u - 192;
                    int r2 = gu / 48, k0i = (gu % 48) * 4;
                    int r0 = rb + r2 * 2;
                    const float4* w4 = (const float4*)(W_hh + k0i);
                    float4 bb = *(const float4*)(b_hh + k0i);
                    float4 a0 = bb, a1 = bb;
                    #pragma unroll 8
                    for (int i = 0; i < Hd; i++) {
                        float xa = sh[r0][i], xb = sh[r0 + 1][i];
                        float4 wv = w4[i * 48];
                        a0.x=fmaf(xa,wv.x,a0.x); a0.y=fmaf(xa,wv.y,a0.y); a0.z=fmaf(xa,wv.z,a0.z); a0.w=fmaf(xa,wv.w,a0.w);
                        a1.x=fmaf(xb,wv.x,a1.x); a1.y=fmaf(xb,wv.y,a1.y); a1.z=fmaf(xb,wv.z,a1.z); a1.w=fmaf(xb,wv.w,a1.w);
                    }
                    *(float4*)&S_GH(r2 * 2, k0i)     = a0;
                    *(float4*)&S_GH(r2 * 2 + 1, k0i) = a1;
                }
            }
            __syncthreads();
            for (int idx = tid; idx < 512; idx += 256) {
                int lr = idx >> 6, j = idx & 63;
                int r = rb + lr;
                float ir = S_GI(lr, j), iz = S_GI(lr, Hd + j), in_ = S_GI(lr, 2 * Hd + j);
                float hr = S_GH(lr, j), hz = S_GH(lr, Hd + j), hn  = S_GH(lr, 2 * Hd + j);
                float rg = sigmoidf(ir + hr);
                float zz = sigmoidf(iz + hz);
                float nn = tanhf(fmaf(rg, hn, in_));
                sh[r][j] = (1.0f - zz) * nn + zz * sh[r][j];
            }
            __syncthreads();
        }
    }

    // ---------- epilogue ----------
    for (int u = tid; u < 8 * NZv * 16; u += 256) {
        int r2 = u / 80, rem = u % 80;
        int n = rem >> 4, o0 = (rem & 15) * 4;
        int r0 = r2 * 2;
        const float4* w4 = (const float4*)(Wq1 + (size_t)n * 4096 + o0);
        float4 bb = *(const float4*)(bq1 + n * Hd + o0);
        float4 a0 = bb, a1 = bb;
        #pragma unroll 8
        for (int i = 0; i < Hd; i++) {
            float xa = sh[r0][i], xb = sh[r0 + 1][i];
            float4 wv = w4[i * 16];
            a0.x=fmaf(xa,wv.x,a0.x); a0.y=fmaf(xa,wv.y,a0.y); a0.z=fmaf(xa,wv.z,a0.z); a0.w=fmaf(xa,wv.w,a0.w);
            a1.x=fmaf(xb,wv.x,a1.x); a1.y=fmaf(xb,wv.y,a1.y); a1.z=fmaf(xb,wv.z,a1.z); a1.w=fmaf(xb,wv.w,a1.w);
        }
        float* d0 = &S_H1(r0, n, o0);
        float* d1 = &S_H1(r0 + 1, n, o0);
        d0[0]=fmaxf(a0.x,0.f); d0[1]=fmaxf(a0.y,0.f); d0[2]=fmaxf(a0.z,0.f); d0[3]=fmaxf(a0.w,0.f);
        d1[0]=fmaxf(a1.x,0.f); d1[1]=fmaxf(a1.y,0.f); d1[2]=fmaxf(a1.z,0.f); d1[3]=fmaxf(a1.w,0.f);
    }
    if (tid == 0) {
        while (atomicAdd(&g_done[Tn], 0) < EPS_T_BLOCKS) __nanosleep(200);
        __threadfence();
    }
    __syncthreads();
    for (int u = tid; u < Rr * 32; u += 256) {
        int r = u >> 5, z0 = (u & 31) * 2;
        float m0 = 0.f, m1 = 0.f;
        for (int n = 0; n < NZv; n++) {
            float t0a = bq2[n * Hd + z0], t1a = bq2[n * Hd + z0 + 1];
            const float2* w2 = (const float2*)(Wq2 + (size_t)n * 4096 + z0);
            #pragma unroll 8
            for (int o = 0; o < Hd; o++) {
                float hv = S_H1(r, n, o);
                float2 wv = w2[o * 32];
                t0a = fmaf(hv, wv.x, t0a);
                t1a = fmaf(hv, wv.y, t1a);
            }
            float g = gprior[n];
            m0 = fmaf(g, t0a, m0);
            m1 = fmaf(g, t1a, m1);
        }
        const float* ep = g_eps + ((size_t)Tn * Bn + row0 + r) * Hd + z0;
        S_Z(r, z0)     = fmaf(softplusf(m0), ep[0], fmaxf(m0, 0.f));
        S_Z(r, z0 + 1) = fmaf(softplusf(m1), ep[1], fmaxf(m1, 0.f));
    }
    __syncthreads();
    for (int u = tid; u < Rr * 32; u += 256) {
        int r = u >> 5, j0 = (u & 31) * 2;
        float a0 = b_z[j0], a1 = b_z[j0 + 1];
        const float2* w2 = (const float2*)(W_z + j0);
        #pragma unroll 8
        for (int i = 0; i < Hd; i++) {
            float xv = S_Z(r, i);
            float2 wv = w2[i * 32];
            a0 = fmaf(xv, wv.x, a0);
            a1 = fmaf(xv, wv.y, a1);
        }
        S_PZ(r, j0)     = fmaxf(a0, 0.f);
        S_PZ(r, j0 + 1) = fmaxf(a1, 0.f);
    }
    __syncthreads();
    for (int u = tid; u < Rr * 32; u += 256) {
        int r = u >> 5, j0 = (u & 31) * 2;
        float a0 = b_dec[j0], a1 = b_dec[j0 + 1];
        const float2* w2 = (const float2*)(W_dec + j0);
        #pragma unroll 8
        for (int i = 0; i < Hd; i++) {
            float xv = S_PZ(r, i);
            float2 wv = w2[i * 32];
            a0 = fmaf(xv, wv.x, a0);
            a1 = fmaf(xv, wv.y, a1);
        }
        #pragma unroll 8
        for (int i = 0; i < Hd; i++) {
            float xv = sh[r][i];
            float2 wv = w2[(Hd + i) * 32];
            a0 = fmaf(xv, wv.x, a0);
            a1 = fmaf(xv, wv.y, a1);
        }
        sx[r][j0]     = fmaxf(a0, 0.f);
        sx[r][j0 + 1] = fmaxf(a1, 0.f);
    }
    __syncthreads();
    for (int u = tid; u < Rr * ACTD; u += 256) {
        int r = u / ACTD, a = u % ACTD;
        float acc = b_a[a];
        #pragma unroll 8
        for (int j = 0; j < Hd; j++) acc = fmaf(sx[r][j], W_a[j * ACTD + a], acc);
        s_logit[r][a] = acc;
        out[(size_t)(row0 + r) * ACTD + a] = acc;
    }
    __syncthreads();
    for (int u = tid; u < Rr * 32; u += 256) {
        int r = u >> 5, j0 = (u & 31) * 2;
        float a0 = b_act[j0], a1 = b_act[j0 + 1];
        const float2* w2 = (const float2*)(W_act + j0);
        #pragma unroll
        for (int a = 0; a < ACTD; a++) {
            float xv = s_logit[r][a];
            float2 wv = w2[a * 32];
            a0 = fmaf(xv, wv.x, a0);
            a1 = fmaf(xv, wv.y, a1);
        }
        s_mp[r][j0]     = fmaxf(a0, 0.f);
        s_mp[r][j0 + 1] = fmaxf(a1, 0.f);
    }
    __syncthreads();
    if (tid < Rr) {
        int r = tid;
        float acc = b_durd[0];
        #pragma unroll 8
        for (int j = 0; j < Hd; j++) acc = fmaf(s_mp[r][j], W_durd[j], acc);
        #pragma unroll 8
        for (int j = 0; j < Hd; j++) acc = fmaf(sx[r][j], W_durd[Hd + j], acc);
        out[(size_t)Bn * ACTD + row0 + r] = acc;
        out[(size_t)Bn * ACTD + Bn + row0 + r] = softplusf(acc);
    }
    __syncthreads();

    // ---------- block-wide KL reduction ----------
    {
        float* rs = (float*)u_buf;
        rs[tid] = kl_acc;
        __syncthreads();
        for (int st = 128; st > 0; st >>= 1) {
            if (tid < st) rs[tid] += rs[tid + st];
            __syncthreads();
        }
        if (tid == 0) g_kld[sb] = rs[0];
    }

    // ---------- finalization ----------
    __threadfence();
    __syncthreads();
    if (tid == 0) atomicAdd(&g_scan_done, 1);

    if (sb == 0) {
        float* rs = (float*)u_buf;
        if (tid == 0) {
            while (atomicAdd(&g_scan_done, 0) < SCAN_BLOCKS) __nanosleep(200);
            __threadfence();
        }
        __syncthreads();
        rs[tid] = (tid < SCAN_BLOCKS) ? g_kld[tid] : 0.f;
        __syncthreads();
        for (int st = 128; st > 0; st >>= 1) {
            if (tid < st) rs[tid] += rs[tid + st];
            __syncthreads();
        }
        if (tid == 0) out[(size_t)Bn * ACTD + 2 * Bn] = rs[0] * (1.0f / Bn);
        if (tid <= Tn) g_done[tid] = 0;
        if (tid == 0) g_scan_done = 0;
    }
#undef S_INP
#undef S_Z
#undef S_PZ
#undef S_H1
#undef S_GI
#undef S_GH
}

// ============================================================================
// fused kernel: blocks [0,64) = scan (wave-1 resident), rest = eps
// ============================================================================
__global__ void __launch_bounds__(256) fused_kernel(
    const int* __restrict__ acts, const float* __restrict__ durs,
    const float* __restrict__ W_act, const float* __restrict__ b_act,
    const float* __restrict__ W_dur, const float* __restrict__ b_dur,
    const float* __restrict__ W_x,  const float* __restrict__ b_x,
    const float* __restrict__ W_z,  const float* __restrict__ b_z,
    const float* __restrict__ Wp1,  const float* __restrict__ bp1,
    const float* __restrict__ Wp2,  const float* __restrict__ bp2,
    const float* __restrict__ Wq1,  const float* __restrict__ bq1,
    const float* __restrict__ Wq2,  const float* __restrict__ bq2,
    const float* __restrict__ W_dec,const float* __restrict__ b_dec,
    const float* __restrict__ W_a,  const float* __restrict__ b_a,
    const float* __restrict__ W_durd,const float* __restrict__ b_durd,
    const float* __restrict__ W_ih, const float* __restrict__ W_hh,
    const float* __restrict__ b_ih, const float* __restrict__ b_hh,
    const float* __restrict__ gpost,const float* __restrict__ gprior,
    float* __restrict__ out)
{
    if (blockIdx.x >= SCAN_BLOCKS) {
        eps_role(blockIdx.x - SCAN_BLOCKS);
    } else {
        scan_role(blockIdx.x,
                  acts, durs, W_act, b_act, W_dur, b_dur, W_x, b_x, W_z, b_z,
                  Wp1, bp1, Wp2, bp2, Wq1, bq1, Wq2, bq2, W_dec, b_dec,
                  W_a, b_a, W_durd, b_durd, W_ih, W_hh, b_ih, b_hh,
                  gpost, gprior, out);
    }
}

// ---------------- launch ----------------
extern "C" void kernel_launch(void* const* d_in, const int* in_sizes, int n_in,
                              void* d_out, int out_size) {
    const int*   acts   = (const int*)  d_in[0];
    const float* durs   = (const float*)d_in[1];
    const float* W_act  = (const float*)d_in[2];
    const float* b_act  = (const float*)d_in[3];
    const float* W_dur  = (const float*)d_in[4];
    const float* b_dur  = (const float*)d_in[5];
    const float* W_x    = (const float*)d_in[6];
    const float* b_x    = (const float*)d_in[7];
    const float* W_z    = (const float*)d_in[8];
    const float* b_z    = (const float*)d_in[9];
    const float* Wp1    = (const float*)d_in[10];
    const float* bp1    = (const float*)d_in[11];
    const float* Wp2    = (const float*)d_in[12];
    const float* bp2    = (const float*)d_in[13];
    const float* Wq1    = (const float*)d_in[14];
    const float* bq1    = (const float*)d_in[15];
    const float* Wq2    = (const float*)d_in[16];
    const float* bq2    = (const float*)d_in[17];
    const float* W_dec  = (const float*)d_in[18];
    const float* b_dec  = (const float*)d_in[19];
    const float* W_a    = (const float*)d_in[20];
    const float* b_a    = (const float*)d_in[21];
    const float* W_durd = (const float*)d_in[22];
    const float* b_durd = (const float*)d_in[23];
    const float* W_ih   = (const float*)d_in[24];
    const float* W_hh   = (const float*)d_in[25];
    const float* b_ih   = (const float*)d_in[26];
    const float* b_hh   = (const float*)d_in[27];
    const float* gpost  = (const float*)d_in[28];
    const float* gprior = (const float*)d_in[29];
    float* out = (float*)d_out;

    fused_kernel<<<SCAN_BLOCKS + EPS_TOTAL, 256>>>(
        acts, durs, W_act, b_act, W_dur, b_dur, W_x, b_x, W_z, b_z,
        Wp1, bp1, Wp2, bp2, Wq1, bq1, Wq2, bq2, W_dec, b_dec,
        W_a, b_a, W_durd, b_durd, W_ih, W_hh, b_ih, b_hh,
        gpost, gprior, out);
}

// round 16
// speedup vs baseline: 1.1152x; 1.0274x over previous
#include <cuda_runtime.h>

#define Bn 1024
#define Tn 128
#define Hd 64
#define NZv 5
#define ACTD 20
#define Rr 16
#define SCAN_BLOCKS 64
#define EPS_T_BLOCKS 256                     // 256 blocks x 256 threads = 65536 outputs per timestep
#define EPS_TOTAL ((Tn + 1) * EPS_T_BLOCKS)  // 33024 eps blocks

typedef unsigned long long ull;

// ---------------- device scratch (static allocation only) ----------------
__device__ float g_eps[(size_t)(Tn + 1) * Bn * Hd];     // (T+1,B,H)
__device__ float g_kld[SCAN_BLOCKS];                    // per-block partial sums
__device__ int   g_done[Tn + 1];                        // zero-init at load; reset by reducer
__device__ int   g_scan_done;                           // ditto
__device__ unsigned g_one = 1;   // runtime-opaque 1: forces adds onto IMAD (fma pipe)

// ---------------- f32x2 packed helpers ----------------
__device__ __forceinline__ ull pk2(float lo, float hi) {
    ull r; asm("mov.b64 %0, {%1, %2};" : "=l"(r) : "f"(lo), "f"(hi)); return r;
}
__device__ __forceinline__ void unpk2(ull v, float& lo, float& hi) {
    asm("mov.b64 {%0, %1}, %2;" : "=f"(lo), "=f"(hi) : "l"(v));
}
__device__ __forceinline__ ull pki2(unsigned lo, unsigned hi) {
    ull r; asm("mov.b64 %0, {%1, %2};" : "=l"(r) : "r"(lo), "r"(hi)); return r;
}
__device__ __forceinline__ ull fma2(ull a, ull b, ull c) {
    ull d; asm("fma.rn.f32x2 %0, %1, %2, %3;" : "=l"(d) : "l"(a), "l"(b), "l"(c)); return d;
}
__device__ __forceinline__ ull add2(ull a, ull b) {
    ull d; asm("add.rn.f32x2 %0, %1, %2;" : "=l"(d) : "l"(a), "l"(b)); return d;
}
__device__ __forceinline__ ull dup2(float x) { return pk2(x, x); }

// ---------------- math helpers ----------------
__device__ __forceinline__ float softplusf(float x) {
    return fmaxf(x, 0.0f) + log1pf(expf(-fabsf(x)));
}
__device__ __forceinline__ float sigmoidf(float x) {
    return 1.0f / (1.0f + expf(-x));
}
__device__ __forceinline__ unsigned imadd(unsigned a, unsigned b, unsigned one) {
    unsigned d;
    asm("mad.lo.u32 %0, %1, %2, %3;" : "=r"(d) : "r"(a), "r"(one), "r"(b));
    return d;
}
__device__ __forceinline__ float poly_main(float wk) {
    float p = 2.81022636e-08f;
    p = fmaf(p, wk, 3.43273939e-07f);
    p = fmaf(p, wk, -3.5233877e-06f);
    p = fmaf(p, wk, -4.39150654e-06f);
    p = fmaf(p, wk, 0.00021858087f);
    p = fmaf(p, wk, -0.00125372503f);
    p = fmaf(p, wk, -0.00417768164f);
    p = fmaf(p, wk, 0.246640727f);
    p = fmaf(p, wk, 1.50140941f);
    return p;
}
__device__ __forceinline__ float poly_tail(float w) {
    float ws = sqrtf(w) - 3.0f;
    float p = -0.000200214257f;
    p = fmaf(p, ws, 0.000100950558f);
    p = fmaf(p, ws, 0.00134934322f);
    p = fmaf(p, ws, -0.00367342844f);
    p = fmaf(p, ws, 0.00573950773f);
    p = fmaf(p, ws, -0.0076224613f);
    p = fmaf(p, ws, 0.00943887047f);
    p = fmaf(p, ws, 1.00167406f);
    p = fmaf(p, ws, 2.83297682f);
    return p;
}

// general threefry (prologue key fold only)
__device__ __forceinline__ uint2 threefry2x32(unsigned k0, unsigned k1,
                                              unsigned x0, unsigned x1) {
    unsigned ks2 = k0 ^ k1 ^ 0x1BD11BDAu;
#define TF_RND(r) { x0 += x1; x1 = __funnelshift_l(x1, x1, r); x1 ^= x0; }
    x0 += k0; x1 += k1;
    TF_RND(13) TF_RND(15) TF_RND(26) TF_RND(6)
    x0 += k1;  x1 += ks2 + 1u;
    TF_RND(17) TF_RND(29) TF_RND(16) TF_RND(24)
    x0 += ks2; x1 += k0 + 2u;
    TF_RND(13) TF_RND(15) TF_RND(26) TF_RND(6)
    x0 += k0;  x1 += k1 + 3u;
    TF_RND(17) TF_RND(29) TF_RND(16) TF_RND(24)
    x0 += k1;  x1 += ks2 + 4u;
    TF_RND(13) TF_RND(15) TF_RND(26) TF_RND(6)
    x0 += ks2; x1 += k0 + 5u;
#undef TF_RND
    uint2 r; r.x = x0; r.y = x1; return r;
}

// hot path (R12 champion): counter word0 == 0, standalone adds as IMAD
// (fma pipe), rotate/xor SHF+LOP3 (alu). Returns y0 ^ y1.
__device__ __forceinline__ unsigned tf_xor(
    unsigned k0, unsigned k1, unsigned ks2,
    unsigned c1, unsigned c2, unsigned c3, unsigned c4, unsigned c5,
    unsigned e, unsigned k1d, unsigned one)
{
    unsigned x0 = k0;
    unsigned x1 = imadd(e, k1d, one);
#define TF_S(r) { x0 = imadd(x1, x0, one); x1 = __funnelshift_l(x1, x1, r); x1 ^= x0; }
    TF_S(13) TF_S(15) TF_S(26) TF_S(6)
    x0 = imadd(k1, x0, one);  x1 = imadd(c1, x1, one);
    TF_S(17) TF_S(29) TF_S(16) TF_S(24)
    x0 = imadd(ks2, x0, one); x1 = imadd(c2, x1, one);
    TF_S(13) TF_S(15) TF_S(26) TF_S(6)
    x0 = imadd(k0, x0, one);  x1 = imadd(c3, x1, one);
    TF_S(17) TF_S(29) TF_S(16) TF_S(24)
    x0 = imadd(k1, x0, one);  x1 = imadd(c4, x1, one);
    TF_S(13) TF_S(15) TF_S(26) TF_S(6)
    x0 = imadd(ks2, x0, one); x1 = imadd(c5, x1, one);
#undef TF_S
    return x0 ^ x1;
}

// mantissa word via funnel shift: (bits>>9) | 0x3F800000 in ONE SHF
__device__ __forceinline__ unsigned mant(unsigned bits) {
    return __funnelshift_r(bits, 0x7Fu, 9);
}

// ============================================================================
// EPS role (R12 champion: exact reference float path, bit-identical)
// ============================================================================
__device__ __noinline__ void eps_role(int eb) {
    const int tid = threadIdx.x;
    const int t = eb >> 8;
    const unsigned bz = (unsigned)((eb & 255) * 256 + tid);
    const int gid = t * (Bn * Hd) + (int)bz;

    const unsigned one = g_one;
    uint2 kk = threefry2x32(0u, 42u, 0u, (unsigned)t);
    const unsigned k0 = kk.x, k1 = kk.y;
    const unsigned ks2 = k0 ^ k1 ^ 0x1BD11BDAu;
    const unsigned c1 = ks2 + 1u, c2 = k0 + 2u, c3 = k1 + 3u,
                   c4 = ks2 + 4u, c5 = k0 + 5u;
    const unsigned k1d0 = k1, k1d1 = k1 + 65536u,
                   k1d2 = k1 + 131072u, k1d3 = k1 + 196608u;

    const ull NEGONE2  = dup2(-1.0f);
    const ull TWO2     = dup2(2.0f);
    const ull NEGP2    = dup2(-0.99999994f);
    const ull NEGLN2_2 = dup2(-0.69314718f);
    const ull M2P5_2   = dup2(-2.5f);
    const ull P0 = dup2(2.81022636e-08f);
    const ull P1 = dup2(3.43273939e-07f);
    const ull P2 = dup2(-3.5233877e-06f);
    const ull P3 = dup2(-4.39150654e-06f);
    const ull P4 = dup2(0.00021858087f);
    const ull P5 = dup2(-0.00125372503f);
    const ull P6 = dup2(-0.00417768164f);
    const ull P7 = dup2(0.246640727f);
    const ull P8 = dup2(1.50140941f);

    ull sumA = 0ull, sumB = 0ull;
    unsigned e = bz;
    const unsigned step = 262144u;

    #pragma unroll 2
    for (int s = 0; s < 250; s++) {
        unsigned b0 = tf_xor(k0, k1, ks2, c1, c2, c3, c4, c5, e, k1d0, one);
        unsigned b1 = tf_xor(k0, k1, ks2, c1, c2, c3, c4, c5, e, k1d1, one);
        unsigned b2 = tf_xor(k0, k1, ks2, c1, c2, c3, c4, c5, e, k1d2, one);
        unsigned b3 = tf_xor(k0, k1, ks2, c1, c2, c3, c4, c5, e, k1d3, one);

        ull gA = pki2(mant(b0), mant(b1));
        ull gB = pki2(mant(b2), mant(b3));
        ull fA = add2(gA, NEGONE2);          // exact: g-1 (Sterbenz)
        ull fB = add2(gB, NEGONE2);
        ull uA = fma2(fA, TWO2, NEGP2);      // 2f - 0.99999994 (== reference)
        ull uB = fma2(fB, TWO2, NEGP2);
        ull tA = fma2(uA, uA, NEGONE2);      // u^2 - 1 = -(1-u^2), exact negation
        ull tB = fma2(uB, uB, NEGONE2);
        float t0, t1, t2, t3;
        unpk2(tA, t0, t1); unpk2(tB, t2, t3);
        float tm = fmaxf(fmaxf(t0, t1), fmaxf(t2, t3));

        if (__builtin_expect(tm >= -6.737947e-3f, 0)) {
            float u0, u1, u2, u3;
            unpk2(uA, u0, u1); unpk2(uB, u2, u3);
            float uu[4] = {u0, u1, u2, u3};
            float tt[4] = {t0, t1, t2, t3};
            float cc[4];
            #pragma unroll
            for (int i = 0; i < 4; i++) {
                float l = __log2f(-tt[i]);
                float w = l * -0.69314718f;
                float pv;
                if (w < 5.0f) pv = poly_main(fmaf(l, -0.69314718f, -2.5f));
                else          pv = poly_tail(w);
                cc[i] = pv * uu[i];
            }
            sumA = add2(sumA, pk2(cc[0], cc[1]));
            sumB = add2(sumB, pk2(cc[2], cc[3]));
        } else {
            float l0 = __log2f(-t0), l1 = __log2f(-t1);
            float l2 = __log2f(-t2), l3 = __log2f(-t3);
            ull wkA = fma2(pk2(l0, l1), NEGLN2_2, M2P5_2);
            ull wkB = fma2(pk2(l2, l3), NEGLN2_2, M2P5_2);
            ull pA = fma2(P0, wkA, P1);
            ull pB = fma2(P0, wkB, P1);
            pA = fma2(pA, wkA, P2);  pB = fma2(pB, wkB, P2);
            pA = fma2(pA, wkA, P3);  pB = fma2(pB, wkB, P3);
            pA = fma2(pA, wkA, P4);  pB = fma2(pB, wkB, P4);
            pA = fma2(pA, wkA, P5);  pB = fma2(pB, wkB, P5);
            pA = fma2(pA, wkA, P6);  pB = fma2(pB, wkB, P6);
            pA = fma2(pA, wkA, P7);  pB = fma2(pB, wkB, P7);
            pA = fma2(pA, wkA, P8);  pB = fma2(pB, wkB, P8);
            sumA = fma2(pA, uA, sumA);
            sumB = fma2(pB, uB, sumB);
        }
        e = imadd(step, e, one);
    }
    float s0, s1, s2, s3;
    unpk2(sumA, s0, s1); unpk2(sumB, s2, s3);
    g_eps[gid] = ((s0 + s1) + (s2 + s3)) * (1.41421356f * 0.001f);

    __threadfence();
    __syncthreads();
    if (tid == 0) atomicAdd(&g_done[t], 1);
}

// ============================================================================
// SCAN role: 16 rows/block, 64 blocks (R12, unchanged)
// ============================================================================
__device__ void scan_role(
    int sb,
    const int* __restrict__ acts, const float* __restrict__ durs,
    const float* __restrict__ W_act, const float* __restrict__ b_act,
    const float* __restrict__ W_dur, const float* __restrict__ b_dur,
    const float* __restrict__ W_x,  const float* __restrict__ b_x,
    const float* __restrict__ W_z,  const float* __restrict__ b_z,
    const float* __restrict__ Wp1,  const float* __restrict__ bp1,
    const float* __restrict__ Wp2,  const float* __restrict__ bp2,
    const float* __restrict__ Wq1,  const float* __restrict__ bq1,
    const float* __restrict__ Wq2,  const float* __restrict__ bq2,
    const float* __restrict__ W_dec,const float* __restrict__ b_dec,
    const float* __restrict__ W_a,  const float* __restrict__ b_a,
    const float* __restrict__ W_durd,const float* __restrict__ b_durd,
    const float* __restrict__ W_ih, const float* __restrict__ W_hh,
    const float* __restrict__ b_ih, const float* __restrict__ b_hh,
    const float* __restrict__ gpost,const float* __restrict__ gprior,
    float* __restrict__ out)
{
    __shared__ float sh[Rr][Hd];
    __shared__ float sx[Rr][Hd];
    __shared__ float u_buf[Rr][2 * Hd];
    __shared__ float u_big[Rr * NZv * Hd];
    __shared__ float s_mp[Rr][Hd];
    __shared__ float s_mq[Rr][Hd];
    __shared__ float s_logit[Rr][ACTD];

#define S_INP(r,c)  u_buf[r][c]
#define S_Z(r,j)    u_buf[r][j]
#define S_PZ(r,j)   u_buf[r][Hd + (j)]
#define S_H1(r,n,o) u_big[(((r) * NZv) + (n)) * Hd + (o)]
#define S_GI(lr,k)  u_big[(lr) * 192 + (k)]
#define S_GH(lr,k)  u_big[1536 + (lr) * 192 + (k)]

    const int tid = threadIdx.x;
    const int row0 = sb * Rr;
    float kl_acc = 0.0f;

    for (int idx = tid; idx < Rr * Hd; idx += 256) sh[idx >> 6][idx & 63] = 0.f;
    __syncthreads();

    for (int t = 0; t < Tn; t++) {
        for (int idx = tid; idx < Rr * 2 * Hd; idx += 256) {
            int r = idx >> 7, c = idx & 127;
            float v;
            if (c < Hd) {
                int a = acts[(row0 + r) * Tn + t];
                v = W_act[a * Hd + c] + b_act[c];
            } else {
                float du = durs[(row0 + r) * Tn + t];
                v = fmaf(du, W_dur[c - Hd], b_dur[c - Hd]);
            }
            S_INP(r, c) = fmaxf(v, 0.f);
        }
        __syncthreads();

        for (int u = tid; u < Rr * 32; u += 256) {
            int r = u >> 5, j0 = (u & 31) * 2;
            float a0 = b_x[j0], a1 = b_x[j0 + 1];
            const float2* w2 = (const float2*)(W_x + j0);
            #pragma unroll 8
            for (int i = 0; i < 2 * Hd; i++) {
                float xv = S_INP(r, i);
                float2 wv = w2[i * 32];
                a0 = fmaf(xv, wv.x, a0);
                a1 = fmaf(xv, wv.y, a1);
            }
            sx[r][j0]     = fmaxf(a0, 0.f);
            sx[r][j0 + 1] = fmaxf(a1, 0.f);
        }
        __syncthreads();

        for (int u = tid; u < 8 * NZv * 16; u += 256) {
            int r2 = u / 80, rem = u % 80;
            int n = rem >> 4, o0 = (rem & 15) * 4;
            int r0 = r2 * 2;
            const float4* w4 = (const float4*)(Wp1 + (size_t)n * 8192 + o0);
            float4 bb = *(const float4*)(bp1 + n * Hd + o0);
            float4 a0 = bb, a1 = bb;
            #pragma unroll 8
            for (int i = 0; i < Hd; i++) {
                float xa = sx[r0][i], xb = sx[r0 + 1][i];
                float4 wv = w4[i * 16];
                a0.x=fmaf(xa,wv.x,a0.x); a0.y=fmaf(xa,wv.y,a0.y); a0.z=fmaf(xa,wv.z,a0.z); a0.w=fmaf(xa,wv.w,a0.w);
                a1.x=fmaf(xb,wv.x,a1.x); a1.y=fmaf(xb,wv.y,a1.y); a1.z=fmaf(xb,wv.z,a1.z); a1.w=fmaf(xb,wv.w,a1.w);
            }
            #pragma unroll 8
            for (int i = 0; i < Hd; i++) {
                float xa = sh[r0][i], xb = sh[r0 + 1][i];
                float4 wv = w4[(Hd + i) * 16];
                a0.x=fmaf(xa,wv.x,a0.x); a0.y=fmaf(xa,wv.y,a0.y); a0.z=fmaf(xa,wv.z,a0.z); a0.w=fmaf(xa,wv.w,a0.w);
                a1.x=fmaf(xb,wv.x,a1.x); a1.y=fmaf(xb,wv.y,a1.y); a1.z=fmaf(xb,wv.z,a1.z); a1.w=fmaf(xb,wv.w,a1.w);
            }
            float* d0 = &S_H1(r0, n, o0);
            float* d1 = &S_H1(r0 + 1, n, o0);
            d0[0]=fmaxf(a0.x,0.f); d0[1]=fmaxf(a0.y,0.f); d0[2]=fmaxf(a0.z,0.f); d0[3]=fmaxf(a0.w,0.f);
            d1[0]=fmaxf(a1.x,0.f); d1[1]=fmaxf(a1.y,0.f); d1[2]=fmaxf(a1.z,0.f); d1[3]=fmaxf(a1.w,0.f);
        }
        __syncthreads();

        for (int u = tid; u < Rr * 32; u += 256) {
            int r = u >> 5, z0 = (u & 31) * 2;
            float m0 = 0.f, m1 = 0.f;
            for (int n = 0; n < NZv; n++) {
                float t0a = bp2[n * Hd + z0], t1a = bp2[n * Hd + z0 + 1];
                const float2* w2 = (const float2*)(Wp2 + (size_t)n * 4096 + z0);
                #pragma unroll 8
                for (int o = 0; o < Hd; o++) {
                    float hv = S_H1(r, n, o);
                    float2 wv = w2[o * 32];
                    t0a = fmaf(hv, wv.x, t0a);
                    t1a = fmaf(hv, wv.y, t1a);
                }
                float g = gpost[n];
                m0 = fmaf(g, t0a, m0);
                m1 = fmaf(g, t1a, m1);
            }
            s_mp[r][z0] = m0; s_mp[r][z0 + 1] = m1;
        }
        __syncthreads();

        for (int u = tid; u < 8 * NZv * 16; u += 256) {
            int r2 = u / 80, rem = u % 80;
            int n = rem >> 4, o0 = (rem & 15) * 4;
            int r0 = r2 * 2;
            const float4* w4 = (const float4*)(Wq1 + (size_t)n * 4096 + o0);
            float4 bb = *(const float4*)(bq1 + n * Hd + o0);
            float4 a0 = bb, a1 = bb;
            #pragma unroll 8
            for (int i = 0; i < Hd; i++) {
                float xa = sh[r0][i], xb = sh[r0 + 1][i];
                float4 wv = w4[i * 16];
                a0.x=fmaf(xa,wv.x,a0.x); a0.y=fmaf(xa,wv.y,a0.y); a0.z=fmaf(xa,wv.z,a0.z); a0.w=fmaf(xa,wv.w,a0.w);
                a1.x=fmaf(xb,wv.x,a1.x); a1.y=fmaf(xb,wv.y,a1.y); a1.z=fmaf(xb,wv.z,a1.z); a1.w=fmaf(xb,wv.w,a1.w);
            }
            float* d0 = &S_H1(r0, n, o0);
            float* d1 = &S_H1(r0 + 1, n, o0);
            d0[0]=fmaxf(a0.x,0.f); d0[1]=fmaxf(a0.y,0.f); d0[2]=fmaxf(a0.z,0.f); d0[3]=fmaxf(a0.w,0.f);
            d1[0]=fmaxf(a1.x,0.f); d1[1]=fmaxf(a1.y,0.f); d1[2]=fmaxf(a1.z,0.f); d1[3]=fmaxf(a1.w,0.f);
        }
        __syncthreads();

        for (int u = tid; u < Rr * 32; u += 256) {
            int r = u >> 5, z0 = (u & 31) * 2;
            float m0 = 0.f, m1 = 0.f;
            for (int n = 0; n < NZv; n++) {
                float t0a = bq2[n * Hd + z0], t1a = bq2[n * Hd + z0 + 1];
                const float2* w2 = (const float2*)(Wq2 + (size_t)n * 4096 + z0);
                #pragma unroll 8
                for (int o = 0; o < Hd; o++) {
                    float hv = S_H1(r, n, o);
                    float2 wv = w2[o * 32];
                    t0a = fmaf(hv, wv.x, t0a);
                    t1a = fmaf(hv, wv.y, t1a);
                }
                float g = gprior[n];
                m0 = fmaf(g, t0a, m0);
                m1 = fmaf(g, t1a, m1);
            }
            s_mq[r][z0] = m0; s_mq[r][z0 + 1] = m1;
        }
        __syncthreads();

        if (tid == 0) {
            while (atomicAdd(&g_done[t], 0) < EPS_T_BLOCKS) __nanosleep(200);
            __threadfence();
        }
        __syncthreads();

        for (int u = tid; u < Rr * 32; u += 256) {
            int r = u >> 5, z0 = (u & 31) * 2;
            const float* ep = g_eps + ((size_t)t * Bn + row0 + r) * Hd + z0;
            #pragma unroll
            for (int q = 0; q < 2; q++) {
                float mp = s_mp[r][z0 + q], mq = s_mq[r][z0 + q];
                float pm = fmaxf(mp, 0.0f), qm = fmaxf(mq, 0.0f);
                float ps = softplusf(mp),   qs = softplusf(mq);
                float d = pm - qm;
                kl_acc += logf(qs / ps) + (ps * ps + d * d) / (2.0f * qs * qs) - 0.5f;
                S_Z(r, z0 + q) = fmaf(ps, ep[q], pm);
            }
        }
        __syncthreads();

        for (int u = tid; u < Rr * 32; u += 256) {
            int r = u >> 5, j0 = (u & 31) * 2;
            float a0 = b_z[j0], a1 = b_z[j0 + 1];
            const float2* w2 = (const float2*)(W_z + j0);
            #pragma unroll 8
            for (int i = 0; i < Hd; i++) {
                float xv = S_Z(r, i);
                float2 wv = w2[i * 32];
                a0 = fmaf(xv, wv.x, a0);
                a1 = fmaf(xv, wv.y, a1);
            }
            S_PZ(r, j0)     = fmaxf(a0, 0.f);
            S_PZ(r, j0 + 1) = fmaxf(a1, 0.f);
        }
        __syncthreads();

        #pragma unroll
        for (int pass = 0; pass < 2; pass++) {
            int rb = pass * 8;
            for (int u = tid; u < 384; u += 256) {
                if (u < 192) {
                    int r2 = u / 48, k0i = (u % 48) * 4;
                    int r0 = rb + r2 * 2;
                    const float4* w4 = (const float4*)(W_ih + k0i);
                    float4 bb = *(const float4*)(b_ih + k0i);
                    float4 a0 = bb, a1 = bb;
                    #pragma unroll 8
                    for (int i = 0; i < Hd; i++) {
                        float xa = sx[r0][i], xb = sx[r0 + 1][i];
                        float4 wv = w4[i * 48];
                        a0.x=fmaf(xa,wv.x,a0.x); a0.y=fmaf(xa,wv.y,a0.y); a0.z=fmaf(xa,wv.z,a0.z); a0.w=fmaf(xa,wv.w,a0.w);
                        a1.x=fmaf(xb,wv.x,a1.x); a1.y=fmaf(xb,wv.y,a1.y); a1.z=fmaf(xb,wv.z,a1.z); a1.w=fmaf(xb,wv.w,a1.w);
                    }
                    #pragma unroll 8
                    for (int i = 0; i < Hd; i++) {
                        float xa = S_PZ(r0, i), xb = S_PZ(r0 + 1, i);
                        float4 wv = w4[(Hd + i) * 48];
                        a0.x=fmaf(xa,wv.x,a0.x); a0.y=fmaf(xa,wv.y,a0.y); a0.z=fmaf(xa,wv.z,a0.z); a0.w=fmaf(xa,wv.w,a0.w);
                        a1.x=fmaf(xb,wv.x,a1.x); a1.y=fmaf(xb,wv.y,a1.y); a1.z=fmaf(xb,wv.z,a1.z); a1.w=fmaf(xb,wv.w,a1.w);
                    }
                    *(float4*)&S_GI(r2 * 2, k0i)     = a0;
                    *(float4*)&S_GI(r2 * 2 + 1, k0i) = a1;
                } else {
                    int gu = u - 192;
                    int r2 = gu / 48, k0i = (gu % 48) * 4;
                    int r0 = rb + r2 * 2;
                    const float4* w4 = (const float4*)(W_hh + k0i);
                    float4 bb = *(const float4*)(b_hh + k0i);
                    float4 a0 = bb, a1 = bb;
                    #pragma unroll 8
                    for (int i = 0; i < Hd; i++) {
                        float xa = sh[r0][i], xb = sh[r0 + 1][i];
                        float4 wv = w4[i * 48];
                        a0.x=fmaf(xa,wv.x,a0.x); a0.y=fmaf(xa,wv.y,a0.y); a0.z=fmaf(xa,wv.z,a0.z); a0.w=fmaf(xa,wv.w,a0.w);
                        a1.x=fmaf(xb,wv.x,a1.x); a1.y=fmaf(xb,wv.y,a1.y); a1.z=fmaf(xb,wv.z,a1.z); a1.w=fmaf(xb,wv.w,a1.w);
                    }
                    *(float4*)&S_GH(r2 * 2, k0i)     = a0;
                    *(float4*)&S_GH(r2 * 2 + 1, k0i) = a1;
                }
            }
            __syncthreads();
            for (int idx = tid; idx < 512; idx += 256) {
                int lr = idx >> 6, j = idx & 63;
                int r = rb + lr;
                float ir = S_GI(lr, j), iz = S_GI(lr, Hd + j), in_ = S_GI(lr, 2 * Hd + j);
                float hr = S_GH(lr, j), hz = S_GH(lr, Hd + j), hn  = S_GH(lr, 2 * Hd + j);
                float rg = sigmoidf(ir + hr);
                float zz = sigmoidf(iz + hz);
                float nn = tanhf(fmaf(rg, hn, in_));
                sh[r][j] = (1.0f - zz) * nn + zz * sh[r][j];
            }
            __syncthreads();
        }
    }

    // ---------- epilogue ----------
    for (int u = tid; u < 8 * NZv * 16; u += 256) {
        int r2 = u / 80, rem = u % 80;
        int n = rem >> 4, o0 = (rem & 15) * 4;
        int r0 = r2 * 2;
        const float4* w4 = (const float4*)(Wq1 + (size_t)n * 4096 + o0);
        float4 bb = *(const float4*)(bq1 + n * Hd + o0);
        float4 a0 = bb, a1 = bb;
        #pragma unroll 8
        for (int i = 0; i < Hd; i++) {
            float xa = sh[r0][i], xb = sh[r0 + 1][i];
            float4 wv = w4[i * 16];
            a0.x=fmaf(xa,wv.x,a0.x); a0.y=fmaf(xa,wv.y,a0.y); a0.z=fmaf(xa,wv.z,a0.z); a0.w=fmaf(xa,wv.w,a0.w);
            a1.x=fmaf(xb,wv.x,a1.x); a1.y=fmaf(xb,wv.y,a1.y); a1.z=fmaf(xb,wv.z,a1.z); a1.w=fmaf(xb,wv.w,a1.w);
        }
        float* d0 = &S_H1(r0, n, o0);
        float* d1 = &S_H1(r0 + 1, n, o0);
        d0[0]=fmaxf(a0.x,0.f); d0[1]=fmaxf(a0.y,0.f); d0[2]=fmaxf(a0.z,0.f); d0[3]=fmaxf(a0.w,0.f);
        d1[0]=fmaxf(a1.x,0.f); d1[1]=fmaxf(a1.y,0.f); d1[2]=fmaxf(a1.z,0.f); d1[3]=fmaxf(a1.w,0.f);
    }
    if (tid == 0) {
        while (atomicAdd(&g_done[Tn], 0) < EPS_T_BLOCKS) __nanosleep(200);
        __threadfence();
    }
    __syncthreads();
    for (int u = tid; u < Rr * 32; u += 256) {
        int r = u >> 5, z0 = (u & 31) * 2;
        float m0 = 0.f, m1 = 0.f;
        for (int n = 0; n < NZv; n++) {
            float t0a = bq2[n * Hd + z0], t1a = bq2[n * Hd + z0 + 1];
            const float2* w2 = (const float2*)(Wq2 + (size_t)n * 4096 + z0);
            #pragma unroll 8
            for (int o = 0; o < Hd; o++) {
                float hv = S_H1(r, n, o);
                float2 wv = w2[o * 32];
                t0a = fmaf(hv, wv.x, t0a);
                t1a = fmaf(hv, wv.y, t1a);
            }
            float g = gprior[n];
            m0 = fmaf(g, t0a, m0);
            m1 = fmaf(g, t1a, m1);
        }
        const float* ep = g_eps + ((size_t)Tn * Bn + row0 + r) * Hd + z0;
        S_Z(r, z0)     = fmaf(softplusf(m0), ep[0], fmaxf(m0, 0.f));
        S_Z(r, z0 + 1) = fmaf(softplusf(m1), ep[1], fmaxf(m1, 0.f));
    }
    __syncthreads();
    for (int u = tid; u < Rr * 32; u += 256) {
        int r = u >> 5, j0 = (u & 31) * 2;
        float a0 = b_z[j0], a1 = b_z[j0 + 1];
        const float2* w2 = (const float2*)(W_z + j0);
        #pragma unroll 8
        for (int i = 0; i < Hd; i++) {
            float xv = S_Z(r, i);
            float2 wv = w2[i * 32];
            a0 = fmaf(xv, wv.x, a0);
            a1 = fmaf(xv, wv.y, a1);
        }
        S_PZ(r, j0)     = fmaxf(a0, 0.f);
        S_PZ(r, j0 + 1) = fmaxf(a1, 0.f);
    }
    __syncthreads();
    for (int u = tid; u < Rr * 32; u += 256) {
        int r = u >> 5, j0 = (u & 31) * 2;
        float a0 = b_dec[j0], a1 = b_dec[j0 + 1];
        const float2* w2 = (const float2*)(W_dec + j0);
        #pragma unroll 8
        for (int i = 0; i < Hd; i++) {
            float xv = S_PZ(r, i);
            float2 wv = w2[i * 32];
            a0 = fmaf(xv, wv.x, a0);
            a1 = fmaf(xv, wv.y, a1);
        }
        #pragma unroll 8
        for (int i = 0; i < Hd; i++) {
            float xv = sh[r][i];
            float2 wv = w2[(Hd + i) * 32];
            a0 = fmaf(xv, wv.x, a0);
            a1 = fmaf(xv, wv.y, a1);
        }
        sx[r][j0]     = fmaxf(a0, 0.f);
        sx[r][j0 + 1] = fmaxf(a1, 0.f);
    }
    __syncthreads();
    for (int u = tid; u < Rr * ACTD; u += 256) {
        int r = u / ACTD, a = u % ACTD;
        float acc = b_a[a];
        #pragma unroll 8
        for (int j = 0; j < Hd; j++) acc = fmaf(sx[r][j], W_a[j * ACTD + a], acc);
        s_logit[r][a] = acc;
        out[(size_t)(row0 + r) * ACTD + a] = acc;
    }
    __syncthreads();
    for (int u = tid; u < Rr * 32; u += 256) {
        int r = u >> 5, j0 = (u & 31) * 2;
        float a0 = b_act[j0], a1 = b_act[j0 + 1];
        const float2* w2 = (const float2*)(W_act + j0);
        #pragma unroll
        for (int a = 0; a < ACTD; a++) {
            float xv = s_logit[r][a];
            float2 wv = w2[a * 32];
            a0 = fmaf(xv, wv.x, a0);
            a1 = fmaf(xv, wv.y, a1);
        }
        s_mp[r][j0]     = fmaxf(a0, 0.f);
        s_mp[r][j0 + 1] = fmaxf(a1, 0.f);
    }
    __syncthreads();
    if (tid < Rr) {
        int r = tid;
        float acc = b_durd[0];
        #pragma unroll 8
        for (int j = 0; j < Hd; j++) acc = fmaf(s_mp[r][j], W_durd[j], acc);
        #pragma unroll 8
        for (int j = 0; j < Hd; j++) acc = fmaf(sx[r][j], W_durd[Hd + j], acc);
        out[(size_t)Bn * ACTD + row0 + r] = acc;
        out[(size_t)Bn * ACTD + Bn + row0 + r] = softplusf(acc);
    }
    __syncthreads();

    // ---------- block-wide KL reduction ----------
    {
        float* rs = (float*)u_buf;
        rs[tid] = kl_acc;
        __syncthreads();
        for (int st = 128; st > 0; st >>= 1) {
            if (tid < st) rs[tid] += rs[tid + st];
            __syncthreads();
        }
        if (tid == 0) g_kld[sb] = rs[0];
    }

    // ---------- finalization ----------
    __threadfence();
    __syncthreads();
    if (tid == 0) atomicAdd(&g_scan_done, 1);

    if (sb == 0) {
        float* rs = (float*)u_buf;
        if (tid == 0) {
            while (atomicAdd(&g_scan_done, 0) < SCAN_BLOCKS) __nanosleep(200);
            __threadfence();
        }
        __syncthreads();
        rs[tid] = (tid < SCAN_BLOCKS) ? g_kld[tid] : 0.f;
        __syncthreads();
        for (int st = 128; st > 0; st >>= 1) {
            if (tid < st) rs[tid] += rs[tid + st];
            __syncthreads();
        }
        if (tid == 0) out[(size_t)Bn * ACTD + 2 * Bn] = rs[0] * (1.0f / Bn);
        if (tid <= Tn) g_done[tid] = 0;
        if (tid == 0) g_scan_done = 0;
    }
#undef S_INP
#undef S_Z
#undef S_PZ
#undef S_H1
#undef S_GI
#undef S_GH
}

// ============================================================================
// fused kernel: blocks [0,64) = scan (wave-1 resident), rest = eps
// ============================================================================
__global__ void __launch_bounds__(256) fused_kernel(
    const int* __restrict__ acts, const float* __restrict__ durs,
    const float* __restrict__ W_act, const float* __restrict__ b_act,
    const float* __restrict__ W_dur, const float* __restrict__ b_dur,
    const float* __restrict__ W_x,  const float* __restrict__ b_x,
    const float* __restrict__ W_z,  const float* __restrict__ b_z,
    const float* __restrict__ Wp1,  const float* __restrict__ bp1,
    const float* __restrict__ Wp2,  const float* __restrict__ bp2,
    const float* __restrict__ Wq1,  const float* __restrict__ bq1,
    const float* __restrict__ Wq2,  const float* __restrict__ bq2,
    const float* __restrict__ W_dec,const float* __restrict__ b_dec,
    const float* __restrict__ W_a,  const float* __restrict__ b_a,
    const float* __restrict__ W_durd,const float* __restrict__ b_durd,
    const float* __restrict__ W_ih, const float* __restrict__ W_hh,
    const float* __restrict__ b_ih, const float* __restrict__ b_hh,
    const float* __restrict__ gpost,const float* __restrict__ gprior,
    float* __restrict__ out)
{
    if (blockIdx.x >= SCAN_BLOCKS) {
        eps_role(blockIdx.x - SCAN_BLOCKS);
    } else {
        scan_role(blockIdx.x,
                  acts, durs, W_act, b_act, W_dur, b_dur, W_x, b_x, W_z, b_z,
                  Wp1, bp1, Wp2, bp2, Wq1, bq1, Wq2, bq2, W_dec, b_dec,
                  W_a, b_a, W_durd, b_durd, W_ih, W_hh, b_ih, b_hh,
                  gpost, gprior, out);
    }
}

// ---------------- launch ----------------
extern "C" void kernel_launch(void* const* d_in, const int* in_sizes, int n_in,
                              void* d_out, int out_size) {
    const int*   acts   = (const int*)  d_in[0];
    const float* durs   = (const float*)d_in[1];
    const float* W_act  = (const float*)d_in[2];
    const float* b_act  = (const float*)d_in[3];
    const float* W_dur  = (const float*)d_in[4];
    const float* b_dur  = (const float*)d_in[5];
    const float* W_x    = (const float*)d_in[6];
    const float* b_x    = (const float*)d_in[7];
    const float* W_z    = (const float*)d_in[8];
    const float* b_z    = (const float*)d_in[9];
    const float* Wp1    = (const float*)d_in[10];
    const float* bp1    = (const float*)d_in[11];
    const float* Wp2    = (const float*)d_in[12];
    const float* bp2    = (const float*)d_in[13];
    const float* Wq1    = (const float*)d_in[14];
    const float* bq1    = (const float*)d_in[15];
    const float* Wq2    = (const float*)d_in[16];
    const float* bq2    = (const float*)d_in[17];
    const float* W_dec  = (const float*)d_in[18];
    const float* b_dec  = (const float*)d_in[19];
    const float* W_a    = (const float*)d_in[20];
    const float* b_a    = (const float*)d_in[21];
    const float* W_durd = (const float*)d_in[22];
    const float* b_durd = (const float*)d_in[23];
    const float* W_ih   = (const float*)d_in[24];
    const float* W_hh   = (const float*)d_in[25];
    const float* b_ih   = (const float*)d_in[26];
    const float* b_hh   = (const float*)d_in[27];
    const float* gpost  = (const float*)d_in[28];
    const float* gprior = (const float*)d_in[29];
    float* out = (float*)d_out;

    fused_kernel<<<SCAN_BLOCKS + EPS_TOTAL, 256>>>(
        acts, durs, W_act, b_act, W_dur, b_dur, W_x, b_x, W_z, b_z,
        Wp1, bp1, Wp2, bp2, Wq1, bq1, Wq2, bq2, W_dec, b_dec,
        W_a, b_a, W_durd, b_durd, W_ih, W_hh, b_ih, b_hh,
        gpost, gprior, out);
}